// round 10
// baseline (speedup 1.0000x reference)
#include <cuda_runtime.h>
#include <cuda_fp16.h>
#include <mma.h>
#include <stdint.h>
#include <math.h>

using namespace nvcuda;

#define NTOK 8192
#define DIM  1024
#define HID  4096
#define NE   8
#define BM   128
#define BN   256                        // N per pair-tile (each CTA stores BN/2 B rows)
#define GM2  2                          // M256 groups per pair (TMEM: GM2*BN = 512 cols)
#define BNW  128                        // wmma fallback N tile
#define BK   32
#define LDSMW (BK + 8)
#define KC   32
#define STG  5
#define A_ST (GM2 * 128 * KC * 2)       // 16384 (per CTA: 2 groups x 128 rows)
#define B_ST (128 * KC * 2)             // 8192  (per CTA: BN/2 rows)
#define STAGE_BYTES (A_ST + B_ST)       // 24576
#define PAD  512
#define MAXG2 (NTOK / 512 + NE)         // 24
#define MAXT (NTOK / BM + NE)
#define SMEM_BYTES (1024 + 1024 + STG * STAGE_BYTES)   // 124928
#define NCONV 32768                     // convert blocks (2*NE*HID*DIM / 2048)

#if defined(__CUDA_ARCH_FEAT_SM103_ALL) || defined(__CUDA_ARCH_FEAT_SM100_ALL) || defined(__CUDA_ARCH_FEAT_SM101_ALL)
#define TC5 1
#else
#define TC5 0
#endif

// ---------------- device scratch ----------------
__device__ int    g_expert[NTOK];
__device__ int    g_count[NE];
__device__ int    g_cursor[NE];
__device__ int    g_off[NE + 1];
__device__ int    g_perm[NTOK];
__device__ int    g_g2_e[MAXG2];
__device__ int    g_g2_r0[MAXG2];
__device__ int    g_tile_e[MAXT];
__device__ int    g_tile_r0[MAXT];
__device__ __half g_xg[(size_t)(NTOK + PAD) * DIM];    // zero-init padding stays zero
__device__ __half g_h [(size_t)(NTOK + PAD) * HID];
__device__ __half g_wup[(size_t)NE * HID * DIM];
__device__ __half g_wdn[(size_t)NE * DIM * HID];

// ---------------- PTX helpers ----------------
__device__ __forceinline__ uint32_t smem_u32(const void* p) {
    uint32_t a;
    asm("{ .reg .u64 t; cvta.to.shared.u64 t, %1; cvt.u32.u64 %0, t; }" : "=r"(a) : "l"(p));
    return a;
}
#if TC5
__device__ __forceinline__ uint32_t ctarank() {
    uint32_t r;
    asm("mov.u32 %0, %%cluster_ctarank;" : "=r"(r));
    return r;
}
__device__ __forceinline__ bool elect1() {
    uint32_t r;
    asm volatile("{\n\t.reg .pred p;\n\telect.sync _|p, 0xFFFFFFFF;\n\tselp.b32 %0,1,0,p;\n\t}" : "=r"(r));
    return r != 0;
}
__device__ __forceinline__ void mbar_init(uint32_t a, uint32_t cnt) {
    asm volatile("mbarrier.init.shared.b64 [%0], %1;" :: "r"(a), "r"(cnt) : "memory");
}
__device__ __forceinline__ void mbar_wait(uint32_t a, uint32_t ph) {
    asm volatile(
        "{\n\t.reg .pred P;\n\t"
        "LW_%=:\n\t"
        "mbarrier.try_wait.parity.acquire.cta.shared::cta.b64 P, [%0], %1, 0x989680;\n\t"
        "@P bra LD_%=;\n\t"
        "bra LW_%=;\n\t"
        "LD_%=:\n\t}"
        :: "r"(a), "r"(ph) : "memory");
}
__device__ __forceinline__ void mbar_arrive_rank0(uint32_t a) {
    asm volatile(
        "{\n\t.reg .b32 ra;\n\t"
        "mapa.shared::cluster.u32 ra, %0, %1;\n\t"
        "mbarrier.arrive.shared::cluster.b64 _, [ra];\n\t}"
        :: "r"(a), "r"(0u) : "memory");
}
__device__ __forceinline__ void cluster_sync() {
    asm volatile("barrier.cluster.arrive.aligned;" ::: "memory");
    asm volatile("barrier.cluster.wait.aligned;" ::: "memory");
}
__device__ __forceinline__ void tmalloc_cg2(uint32_t smem_dst, uint32_t ncols) {
    asm volatile("tcgen05.alloc.cta_group::2.sync.aligned.shared::cta.b32 [%0], %1;"
                 :: "r"(smem_dst), "r"(ncols) : "memory");
}
__device__ __forceinline__ void tmdealloc_cg2(uint32_t tmem, uint32_t ncols) {
    asm volatile("tcgen05.relinquish_alloc_permit.cta_group::2.sync.aligned;");
    asm volatile("tcgen05.dealloc.cta_group::2.sync.aligned.b32 %0, %1;" :: "r"(tmem), "r"(ncols));
}
__device__ __forceinline__ void mma_f16_ss_cg2(uint32_t d, uint64_t ad, uint64_t bd, uint32_t idesc, uint32_t en) {
    asm volatile(
        "{\n\t.reg .pred p;\n\tsetp.ne.u32 p, %5, 0;\n\t"
        "tcgen05.mma.cta_group::2.kind::f16 [%0], %1, %2, %3, {%4,%4,%4,%4,%4,%4,%4,%4}, p;\n\t}"
        :: "r"(d), "l"(ad), "l"(bd), "r"(idesc), "r"(0u), "r"(en) : "memory");
}
__device__ __forceinline__ void tccommit_mc2(uint32_t mbar) {
    asm volatile(
        "tcgen05.commit.cta_group::2.mbarrier::arrive::one.shared::cluster.multicast::cluster.b64 [%0], %1;"
        :: "r"(mbar), "h"((uint16_t)3) : "memory");
}
__device__ __forceinline__ void cpa16(uint32_t dst, const void* src) {
    asm volatile("cp.async.cg.shared.global [%0], [%1], 16;" :: "r"(dst), "l"(src) : "memory");
}
__device__ __forceinline__ void ldtm32(uint32_t* r, uint32_t addr) {
    asm volatile(
        "tcgen05.ld.sync.aligned.32x32b.x32.b32 "
        "{%0, %1, %2, %3, %4, %5, %6, %7, "
        " %8, %9, %10, %11, %12, %13, %14, %15, "
        " %16, %17, %18, %19, %20, %21, %22, %23, "
        " %24, %25, %26, %27, %28, %29, %30, %31}, [%32];"
        : "=r"(r[0]),  "=r"(r[1]),  "=r"(r[2]),  "=r"(r[3]),
          "=r"(r[4]),  "=r"(r[5]),  "=r"(r[6]),  "=r"(r[7]),
          "=r"(r[8]),  "=r"(r[9]),  "=r"(r[10]), "=r"(r[11]),
          "=r"(r[12]), "=r"(r[13]), "=r"(r[14]), "=r"(r[15]),
          "=r"(r[16]), "=r"(r[17]), "=r"(r[18]), "=r"(r[19]),
          "=r"(r[20]), "=r"(r[21]), "=r"(r[22]), "=r"(r[23]),
          "=r"(r[24]), "=r"(r[25]), "=r"(r[26]), "=r"(r[27]),
          "=r"(r[28]), "=r"(r[29]), "=r"(r[30]), "=r"(r[31])
        : "r"(addr));
}
#endif
#define SWZ64(o) ((o) ^ (((o) >> 3) & 0x30))
__device__ __forceinline__ uint64_t mk_desc64(uint32_t addr) {
    return ((uint64_t)4 << 61) | ((uint64_t)1 << 46) | ((uint64_t)32 << 32) |
           ((uint64_t)1 << 16) | ((addr >> 4) & 0x3FFF);
}

// ---------------- fused: weight convert + router ----------------
__global__ void k_pre(const float* __restrict__ Wup, const float* __restrict__ Wdown,
                      const float* __restrict__ x, const float* __restrict__ Wr,
                      const float* __restrict__ br) {
    __shared__ float sW[NE * DIM];
    if (blockIdx.x < NCONV) {
        const size_t HALF = (size_t)NE * HID * DIM;
        size_t base = ((size_t)blockIdx.x * 256 + threadIdx.x) * 8;
        const float* src;
        __half* dst;
        size_t off;
        if (base < HALF) { src = Wup;   dst = g_wup; off = base; }
        else             { src = Wdown; dst = g_wdn; off = base - HALF; }
        float4 v0 = *(const float4*)(src + off);
        float4 v1 = *(const float4*)(src + off + 4);
        __half2 h[4];
        h[0] = __floats2half2_rn(v0.x, v0.y);
        h[1] = __floats2half2_rn(v0.z, v0.w);
        h[2] = __floats2half2_rn(v1.x, v1.y);
        h[3] = __floats2half2_rn(v1.z, v1.w);
        *(int4*)(dst + off) = *(int4*)h;
        return;
    }
    // ---- router blocks ----
    int rb = blockIdx.x - NCONV;        // 0..NTOK/8-1
    for (int i = threadIdx.x; i < NE * DIM; i += 256) sW[i] = Wr[i];
    __syncthreads();

    int warp = threadIdx.x >> 5, lane = threadIdx.x & 31;
    int t = rb * 8 + warp;
    const float4* xr = (const float4*)(x + (size_t)t * DIM);

    float acc[NE];
#pragma unroll
    for (int e = 0; e < NE; e++) acc[e] = 0.f;
#pragma unroll
    for (int p = 0; p < 8; p++) {
        float4 v = xr[p * 32 + lane];
        int c = (p * 32 + lane) * 4;
#pragma unroll
        for (int e = 0; e < NE; e++) {
            const float* w = &sW[e * DIM + c];
            acc[e] += v.x * w[0] + v.y * w[1] + v.z * w[2] + v.w * w[3];
        }
    }
#pragma unroll
    for (int e = 0; e < NE; e++)
#pragma unroll
        for (int o = 16; o; o >>= 1) acc[e] += __shfl_xor_sync(0xffffffffu, acc[e], o);

    if (lane == 0) {
        int best = 0;
        float bv = acc[0] + br[0];
#pragma unroll
        for (int e = 1; e < NE; e++) {
            float v = acc[e] + br[e];
            if (v > bv) { bv = v; best = e; }
        }
        g_expert[t] = best;
        atomicAdd(&g_count[best], 1);
    }
}

// ---------------- init ----------------
__global__ void k_init() {
    int i = threadIdx.x;
    if (i < NE) { g_count[i] = 0; g_cursor[i] = 0; }
}

// ---------------- scan ----------------
__global__ void k_scan() {
    if (threadIdx.x != 0) return;
    int o = 0;
    for (int e = 0; e < NE; e++) { g_off[e] = o; o += g_count[e]; }
    g_off[NE] = o;
    // cg2 pair-groups of 512 rows
    int t = 0;
    for (int e = 0; e < NE; e++) {
        int g2 = (g_count[e] + 511) / 512;
        for (int m = 0; m < g2; m++) { g_g2_e[t] = e; g_g2_r0[t] = g_off[e] + m * 512; t++; }
    }
    for (; t < MAXG2; t++) g_g2_e[t] = -1;
    // wmma fallback 128-row tiles
    int tt = 0;
    for (int e = 0; e < NE; e++) {
        int tiles = (g_count[e] + BM - 1) / BM;
        for (int m = 0; m < tiles; m++) { g_tile_e[tt] = e; g_tile_r0[tt] = g_off[e] + m * BM; tt++; }
    }
    for (; tt < MAXT; tt++) g_tile_e[tt] = -1;
}

// ---------------- gather + fp32->fp16 ----------------
__global__ void k_gather(const float* __restrict__ x) {
    int gw = (blockIdx.x * blockDim.x + threadIdx.x) >> 5;
    int lane = threadIdx.x & 31;
    if (gw >= NTOK) return;
    int t = gw, e = g_expert[t];
    int slot = 0;
    if (lane == 0) {
        int r = atomicAdd(&g_cursor[e], 1);
        slot = g_off[e] + r;
        g_perm[slot] = t;
    }
    slot = __shfl_sync(0xffffffffu, slot, 0);
    const float4* src = (const float4*)(x + (size_t)t * DIM);
    __half2* dst = (__half2*)(g_xg + (size_t)slot * DIM);
#pragma unroll
    for (int p = 0; p < 8; p++) {
        float4 v = src[p * 32 + lane];
        dst[(p * 32 + lane) * 2]     = __floats2half2_rn(v.x, v.y);
        dst[(p * 32 + lane) * 2 + 1] = __floats2half2_rn(v.z, v.w);
    }
}

// ================= cg2 tcgen05 GEMM: pair tile M512 x N256, 5-buffer lookahead-3 =================
// mbar layout: full[j]=sb+8j (count 2, rank0's used), done[j]=sb+64+8j (count 1), tmem ptr sb+128
template<int KTOT, bool UP>
__global__ void __launch_bounds__(256, 1) __cluster_dims__(2, 1, 1)
k_gemm(const float* __restrict__ Wunused, const float* __restrict__ bias,
       float* __restrict__ out) {
#if TC5
    extern __shared__ char smem_raw[];
    char* smem = (char*)(((uintptr_t)smem_raw + 1023) & ~(uintptr_t)1023);
    const int NOUT = UP ? HID : DIM;

    int gi = blockIdx.y;
    int e = g_g2_e[gi];
    if (e < 0) return;                           // whole pair exits together
    int row0 = g_g2_r0[gi], row_end = g_off[e + 1];
    int n0 = (blockIdx.x >> 1) * BN;
    uint32_t rank = ctarank();                   // 0 or 1
    int tid = threadIdx.x, warp = tid >> 5, lane = tid & 31;
    uint32_t sb = smem_u32(smem);

    if (tid == 0) {
#pragma unroll
        for (int j = 0; j < STG; j++) {
            mbar_init(sb + 8 * j, 2);            // full: both CTAs arrive
            mbar_init(sb + 64 + 8 * j, 1);       // done: one commit arrive
        }
    }
    if (warp == 0) tmalloc_cg2(sb + 128, 512);
    __syncthreads();
    uint32_t tmem;
    asm volatile("ld.shared.b32 %0, [%1];" : "=r"(tmem) : "r"(sb + 128));

    cluster_sync();                              // peer mbars valid before cluster arrivals

    const __half* Asrc = UP ? g_xg : g_h;
    const __half* Ag = Asrc + (size_t)row0 * KTOT;
    const __half* Bg = (UP ? g_wup : g_wdn) + (size_t)e * NOUT * KTOT
                       + (size_t)(n0 + rank * 128) * KTOT;    // this CTA's N-half
    const uint32_t idesc = (1u << 4) | ((BN / 8) << 17) | ((256 / 16) << 24);  // f32 acc, M=256
    const int SMA = 1024;

    auto LOAD = [&](int s, int buf) {
        uint32_t st = sb + SMA + buf * STAGE_BYTES;
#pragma unroll
        for (int g = 0; g < GM2; g++) {
            const __half* As = Ag + (size_t)(g * 256 + rank * 128) * KTOT + s * KC;
            uint32_t ab = st + g * 8192;
#pragma unroll
            for (int i = 0; i < 2; i++) {
                int q = tid + i * 256;
                int r = q >> 2, c = q & 3;
                cpa16(ab + SWZ64((uint32_t)(r * 64 + c * 16)),
                      As + (size_t)r * KTOT + c * 8);
            }
        }
        const __half* Bs = Bg + s * KC;
        uint32_t bb = st + A_ST;
#pragma unroll
        for (int i = 0; i < 2; i++) {
            int q = tid + i * 256;
            int r = q >> 2, c = q & 3;
            cpa16(bb + SWZ64((uint32_t)(r * 64 + c * 16)),
                  Bs + (size_t)r * KTOT + c * 8);
        }
    };

    const int NKC = KTOT / KC;                   // UP: 32, DOWN: 128

#pragma unroll
    for (int p = 0; p < 3; p++) { LOAD(p, p); asm volatile("cp.async.commit_group;" ::: "memory"); }

    for (int s = 0; s < NKC; s++) {
        int slot = s % STG;
        if (s >= 2) mbar_wait(sb + 64 + 8 * ((s - 2) % STG), (uint32_t)(((s - 2) / STG) & 1));
        if (s + 3 < NKC) LOAD(s + 3, (s + 3) % STG);
        asm volatile("cp.async.commit_group;" ::: "memory");
        asm volatile("cp.async.wait_group 3;" ::: "memory");
        asm volatile("fence.proxy.async;" ::: "memory");
        __syncthreads();

        if (tid == 0) mbar_arrive_rank0(sb + 8 * slot);    // stage-s data ready in this CTA

        if (rank == 0 && warp == 0 && elect1()) {
            mbar_wait(sb + 8 * slot, (uint32_t)((s / STG) & 1));   // both halves ready
            uint32_t st = sb + SMA + slot * STAGE_BYTES;
            uint64_t bd = mk_desc64(st + A_ST);
#pragma unroll
            for (int g = 0; g < GM2; g++) {
                uint64_t ad = mk_desc64(st + g * 8192);
#pragma unroll
                for (int ks = 0; ks < 2; ks++) {
                    mma_f16_ss_cg2(tmem + g * BN, ad + ks * 2, bd + ks * 2, idesc,
                                   (uint32_t)((s | ks) != 0));
                }
            }
            tccommit_mc2(sb + 64 + 8 * slot);    // arrives at done[slot] in BOTH CTAs
        }
    }
#pragma unroll
    for (int j = 0; j < STG; j++) {
        int sj = (NKC - 1) - ((NKC - 1 - j) % STG);
        mbar_wait(sb + 64 + 8 * j, (uint32_t)((sj / STG) & 1));
    }
    asm volatile("tcgen05.fence::after_thread_sync;" ::: "memory");

    // ---- epilogue: this CTA holds rows [row0 + g*256 + rank*128, +128) per group ----
    int g = warp >> 2;
    int sub = warp & 3;
    const float* bp = bias + (size_t)e * NOUT + n0;
    {
        int row = row0 + g * 256 + (int)rank * 128 + sub * 32 + lane;
        bool ok = row < row_end;
#pragma unroll
        for (int cb = 0; cb < 8; cb++) {
            uint32_t r[32];
            ldtm32(r, tmem + g * BN + cb * 32);
            asm volatile("tcgen05.wait::ld.sync.aligned;" ::: "memory");
            if (ok) {
                int col = cb * 32;
                if (UP) {
                    __half2 o[16];
#pragma unroll
                    for (int j = 0; j < 16; j++) {
                        float v0 = __uint_as_float(r[2 * j])     + bp[col + 2 * j];
                        float v1 = __uint_as_float(r[2 * j + 1]) + bp[col + 2 * j + 1];
                        v0 = v0 / (1.f + __expf(-v0));
                        v1 = v1 / (1.f + __expf(-v1));
                        o[j] = __floats2half2_rn(v0, v1);
                    }
                    int4* dst = (int4*)(g_h + (size_t)row * HID + n0 + col);
#pragma unroll
                    for (int q = 0; q < 4; q++) dst[q] = ((int4*)o)[q];
                } else {
                    int tok = g_perm[row];
                    float4* dst = (float4*)(out + (size_t)tok * DIM + n0 + col);
#pragma unroll
                    for (int q = 0; q < 8; q++) {
                        float4 ov;
                        ov.x = __uint_as_float(r[4 * q + 0]) + bp[col + 4 * q + 0];
                        ov.y = __uint_as_float(r[4 * q + 1]) + bp[col + 4 * q + 1];
                        ov.z = __uint_as_float(r[4 * q + 2]) + bp[col + 4 * q + 2];
                        ov.w = __uint_as_float(r[4 * q + 3]) + bp[col + 4 * q + 3];
                        dst[q] = ov;
                    }
                }
            }
        }
    }
    __syncthreads();
    cluster_sync();                              // peer TMEM/smem no longer needed
    if (warp == 0) tmdealloc_cg2(tmem, 512);
    cluster_sync();
#endif
}

// ================= wmma fallback GEMMs (active only in non-'a' image) =================
__global__ __launch_bounds__(256, 2) void k_up(const float* __restrict__ Wup,
                                               const float* __restrict__ bup) {
#if !TC5
    __shared__ __align__(128) char smem_raw[4 * BM * LDSMW * sizeof(__half)];
    __half (*sA)[BM][LDSMW] = (__half (*)[BM][LDSMW])smem_raw;
    __half (*sB)[BM][LDSMW] = (__half (*)[BM][LDSMW])(smem_raw + 2 * BM * LDSMW * sizeof(__half));
    float* stage_all = (float*)smem_raw;

    int mt = blockIdx.y;
    int e = g_tile_e[mt];
    if (e < 0) return;
    int row0 = g_tile_r0[mt], row_end = g_off[e + 1];
    int n0 = blockIdx.x * BNW;
    int tid = threadIdx.x, warp = tid >> 5, lane = tid & 31;
    int wm = warp >> 2, wn = warp & 3;

    const __half* Ag = g_xg + (size_t)row0 * DIM;
    const float*  Bg = Wup + (size_t)e * HID * DIM + (size_t)n0 * DIM;

    wmma::fragment<wmma::accumulator, 16, 16, 16, float> c[4][2];
#pragma unroll
    for (int i = 0; i < 4; i++)
#pragma unroll
        for (int j = 0; j < 2; j++) wmma::fill_fragment(c[i][j], 0.f);

    int4 ra[2];
    float4 rb[4];

    auto LOADA = [&](int kt) {
#pragma unroll
        for (int i = 0; i < 2; i++) {
            int q = tid + i * 256, r = q >> 2, c8 = q & 3;
            ra[i] = *(const int4*)(Ag + (size_t)r * DIM + kt * BK + c8 * 8);
        }
    };
    auto LOADB = [&](int kt) {
#pragma unroll
        for (int i = 0; i < 4; i++) {
            int q = tid + i * 256, r = q >> 3, c4 = q & 7;
            rb[i] = *(const float4*)(Bg + (size_t)r * DIM + kt * BK + c4 * 4);
        }
    };
    auto STORE = [&](int buf) {
#pragma unroll
        for (int i = 0; i < 2; i++) {
            int q = tid + i * 256, r = q >> 2, c8 = q & 3;
            *(int4*)&sA[buf][r][c8 * 8] = ra[i];
        }
#pragma unroll
        for (int i = 0; i < 4; i++) {
            int q = tid + i * 256, r = q >> 3, c4 = q & 7;
            *(__half2*)&sB[buf][r][c4 * 4]     = __floats2half2_rn(rb[i].x, rb[i].y);
            *(__half2*)&sB[buf][r][c4 * 4 + 2] = __floats2half2_rn(rb[i].z, rb[i].w);
        }
    };
    auto COMP = [&](int buf) {
#pragma unroll
        for (int ks = 0; ks < 2; ks++) {
            wmma::fragment<wmma::matrix_a, 16, 16, 16, __half, wmma::row_major> a[4];
            wmma::fragment<wmma::matrix_b, 16, 16, 16, __half, wmma::col_major> b[2];
#pragma unroll
            for (int i = 0; i < 4; i++)
                wmma::load_matrix_sync(a[i], &sA[buf][wm * 64 + i * 16][ks * 16], LDSMW);
#pragma unroll
            for (int j = 0; j < 2; j++)
                wmma::load_matrix_sync(b[j], &sB[buf][wn * 32 + j * 16][ks * 16], LDSMW);
#pragma unroll
            for (int i = 0; i < 4; i++)
#pragma unroll
                for (int j = 0; j < 2; j++)
                    wmma::mma_sync(c[i][j], a[i], b[j], c[i][j]);
        }
    };

    LOADA(0); LOADB(0); STORE(0); __syncthreads();
    const int NK = DIM / BK;
    for (int kt = 1; kt < NK; kt++) {
        LOADA(kt); LOADB(kt);
        COMP((kt - 1) & 1);
        STORE(kt & 1);
        __syncthreads();
    }
    COMP((NK - 1) & 1);
    __syncthreads();

    float* st = stage_all + warp * 16 * 20;
#pragma unroll
    for (int i = 0; i < 4; i++)
#pragma unroll
        for (int j = 0; j < 2; j++) {
            wmma::store_matrix_sync(st, c[i][j], 20, wmma::mem_row_major);
            __syncwarp();
            int rr = lane >> 1, cbase = (lane & 1) * 8;
            int grow = row0 + wm * 64 + i * 16 + rr;
            if (grow < row_end) {
                int gcol = n0 + wn * 32 + j * 16 + cbase;
                __half2 o[4];
#pragma unroll
                for (int k2 = 0; k2 < 4; k2++) {
                    float v0 = st[rr * 20 + cbase + 2 * k2]     + bup[(size_t)e * HID + gcol + 2 * k2];
                    float v1 = st[rr * 20 + cbase + 2 * k2 + 1] + bup[(size_t)e * HID + gcol + 2 * k2 + 1];
                    v0 = v0 / (1.f + expf(-v0));
                    v1 = v1 / (1.f + expf(-v1));
                    o[k2] = __floats2half2_rn(v0, v1);
                }
                *(int4*)&g_h[(size_t)grow * HID + gcol] = *(int4*)o;
            }
            __syncwarp();
        }
#endif
}

__global__ __launch_bounds__(256, 2) void k_down(const float* __restrict__ Wdown,
                                                 const float* __restrict__ bdown,
                                                 float* __restrict__ out) {
#if !TC5
    __shared__ __align__(128) char smem_raw[4 * BM * LDSMW * sizeof(__half)];
    __half (*sA)[BM][LDSMW] = (__half (*)[BM][LDSMW])smem_raw;
    __half (*sB)[BM][LDSMW] = (__half (*)[BM][LDSMW])(smem_raw + 2 * BM * LDSMW * sizeof(__half));
    float* stage_all = (float*)smem_raw;

    int mt = blockIdx.y;
    int e = g_tile_e[mt];
    if (e < 0) return;
    int row0 = g_tile_r0[mt], row_end = g_off[e + 1];
    int n0 = blockIdx.x * BNW;
    int tid = threadIdx.x, warp = tid >> 5, lane = tid & 31;
    int wm = warp >> 2, wn = warp & 3;

    const __half* Ag = g_h + (size_t)row0 * HID;
    const float*  Bg = Wdown + (size_t)e * DIM * HID + (size_t)n0 * HID;

    wmma::fragment<wmma::accumulator, 16, 16, 16, float> c[4][2];
#pragma unroll
    for (int i = 0; i < 4; i++)
#pragma unroll
        for (int j = 0; j < 2; j++) wmma::fill_fragment(c[i][j], 0.f);

    int4 ra[2];
    float4 rb[4];

    auto LOADA = [&](int kt) {
#pragma unroll
        for (int i = 0; i < 2; i++) {
            int q = tid + i * 256, r = q >> 2, c8 = q & 3;
            ra[i] = *(const int4*)(Ag + (size_t)r * HID + kt * BK + c8 * 8);
        }
    };
    auto LOADB = [&](int kt) {
#pragma unroll
        for (int i = 0; i < 4; i++) {
            int q = tid + i * 256, r = q >> 3, c4 = q & 7;
            rb[i] = *(const float4*)(Bg + (size_t)r * HID + kt * BK + c4 * 4);
        }
    };
    auto STORE = [&](int buf) {
#pragma unroll
        for (int i = 0; i < 2; i++) {
            int q = tid + i * 256, r = q >> 2, c8 = q & 3;
            *(int4*)&sA[buf][r][c8 * 8] = ra[i];
        }
#pragma unroll
        for (int i = 0; i < 4; i++) {
            int q = tid + i * 256, r = q >> 3, c4 = q & 7;
            *(__half2*)&sB[buf][r][c4 * 4]     = __floats2half2_rn(rb[i].x, rb[i].y);
            *(__half2*)&sB[buf][r][c4 * 4 + 2] = __floats2half2_rn(rb[i].z, rb[i].w);
        }
    };
    auto COMP = [&](int buf) {
#pragma unroll
        for (int ks = 0; ks < 2; ks++) {
            wmma::fragment<wmma::matrix_a, 16, 16, 16, __half, wmma::row_major> a[4];
            wmma::fragment<wmma::matrix_b, 16, 16, 16, __half, wmma::col_major> b[2];
#pragma unroll
            for (int i = 0; i < 4; i++)
                wmma::load_matrix_sync(a[i], &sA[buf][wm * 64 + i * 16][ks * 16], LDSMW);
#pragma unroll
            for (int j = 0; j < 2; j++)
                wmma::load_matrix_sync(b[j], &sB[buf][wn * 32 + j * 16][ks * 16], LDSMW);
#pragma unroll
            for (int i = 0; i < 4; i++)
#pragma unroll
                for (int j = 0; j < 2; j++)
                    wmma::mma_sync(c[i][j], a[i], b[j], c[i][j]);
        }
    };

    LOADA(0); LOADB(0); STORE(0); __syncthreads();
    const int NK = HID / BK;
    for (int kt = 1; kt < NK; kt++) {
        LOADA(kt); LOADB(kt);
        COMP((kt - 1) & 1);
        STORE(kt & 1);
        __syncthreads();
    }
    COMP((NK - 1) & 1);
    __syncthreads();

    float* st = stage_all + warp * 16 * 20;
#pragma unroll
    for (int i = 0; i < 4; i++)
#pragma unroll
        for (int j = 0; j < 2; j++) {
            wmma::store_matrix_sync(st, c[i][j], 20, wmma::mem_row_major);
            __syncwarp();
            int rr = lane >> 1, cbase = (lane & 1) * 8;
            int grow = row0 + wm * 64 + i * 16 + rr;
            if (grow < row_end) {
                int tok = g_perm[grow];
                int gcol = n0 + wn * 32 + j * 16 + cbase;
                float4 o0, o1;
                o0.x = st[rr * 20 + cbase + 0] + bdown[(size_t)e * DIM + gcol + 0];
                o0.y = st[rr * 20 + cbase + 1] + bdown[(size_t)e * DIM + gcol + 1];
                o0.z = st[rr * 20 + cbase + 2] + bdown[(size_t)e * DIM + gcol + 2];
                o0.w = st[rr * 20 + cbase + 3] + bdown[(size_t)e * DIM + gcol + 3];
                o1.x = st[rr * 20 + cbase + 4] + bdown[(size_t)e * DIM + gcol + 4];
                o1.y = st[rr * 20 + cbase + 5] + bdown[(size_t)e * DIM + gcol + 5];
                o1.z = st[rr * 20 + cbase + 6] + bdown[(size_t)e * DIM + gcol + 6];
                o1.w = st[rr * 20 + cbase + 7] + bdown[(size_t)e * DIM + gcol + 7];
                *(float4*)&out[(size_t)tok * DIM + gcol]     = o0;
                *(float4*)&out[(size_t)tok * DIM + gcol + 4] = o1;
            }
            __syncwarp();
        }
#endif
}

// ---------------- launcher ----------------
extern "C" void kernel_launch(void* const* d_in, const int* in_sizes, int n_in,
                              void* d_out, int out_size) {
    const float* x     = (const float*)d_in[0];
    const float* Wr    = (const float*)d_in[1];
    const float* br    = (const float*)d_in[2];
    const float* Wup   = (const float*)d_in[3];
    const float* bup   = (const float*)d_in[4];
    const float* Wdown = (const float*)d_in[5];
    const float* bdown = (const float*)d_in[6];
    float* out = (float*)d_out;

    cudaFuncSetAttribute(k_gemm<DIM, true>,  cudaFuncAttributeMaxDynamicSharedMemorySize, SMEM_BYTES);
    cudaFuncSetAttribute(k_gemm<HID, false>, cudaFuncAttributeMaxDynamicSharedMemorySize, SMEM_BYTES);

    k_init<<<1, 32>>>();
    k_pre<<<NCONV + NTOK / 8, 256>>>(Wup, Wdown, x, Wr, br);    // convert + router fused
    k_scan<<<1, 1>>>();
    k_gather<<<NTOK / 8, 256>>>(x);
    k_up<<<dim3(HID / BNW, MAXT), 256>>>(Wup, bup);                                     // empty in 'a'
    k_gemm<DIM, true ><<<dim3(2 * (HID / BN), MAXG2), 256, SMEM_BYTES>>>(Wup, bup, nullptr);
    k_gemm<HID, false><<<dim3(2 * (DIM / BN), MAXG2), 256, SMEM_BYTES>>>(Wdown, bdown, out);
    k_down<<<dim3(DIM / BNW, MAXT), 256>>>(Wdown, bdown, out);                          // empty in 'a'
}

// round 11
// speedup vs baseline: 2.0174x; 2.0174x over previous
#include <cuda_runtime.h>
#include <cuda_fp16.h>
#include <mma.h>
#include <stdint.h>
#include <math.h>

using namespace nvcuda;

#define NTOK 8192
#define DIM  1024
#define HID  4096
#define NE   8
#define BM   128
#define BN   256                        // wide N tile (TMEM: GM*BN = 512 cols)
#define GM   2
#define BNW  128                        // wmma fallback N tile
#define BK   32
#define LDSMW (BK + 8)
#define KC   32
#define STG  5
#define A_ST (GM * BM * KC * 2)         // 16384
#define B_ST (BN * KC * 2)              // 16384
#define STAGE_BYTES (A_ST + B_ST)       // 32768
#define PAD  (GM*BM)
#define MAXG (NTOK / BM / GM + NE)      // 40
#define MAXT (NTOK / BM + NE)
#define SMEM_BYTES (1024 + 1024 + STG * STAGE_BYTES)   // 165888
#define NCONV 32768                     // convert blocks (2*NE*HID*DIM / 2048)

#if defined(__CUDA_ARCH_FEAT_SM103_ALL) || defined(__CUDA_ARCH_FEAT_SM100_ALL) || defined(__CUDA_ARCH_FEAT_SM101_ALL)
#define TC5 1
#else
#define TC5 0
#endif

// ---------------- device scratch ----------------
__device__ int    g_expert[NTOK];
__device__ int    g_count[NE];
__device__ int    g_cursor[NE];
__device__ int    g_off[NE + 1];
__device__ int    g_perm[NTOK];
__device__ int    g_grp_e[MAXG];
__device__ int    g_grp_r0[MAXG];
__device__ int    g_grp_ng[MAXG];
__device__ int    g_tile_e[MAXT];
__device__ int    g_tile_r0[MAXT];
__device__ __half g_xg[(size_t)(NTOK + PAD) * DIM];
__device__ __half g_h [(size_t)(NTOK + PAD) * HID];
__device__ __half g_wup[(size_t)NE * HID * DIM];
__device__ __half g_wdn[(size_t)NE * DIM * HID];

// ---------------- PTX helpers ----------------
__device__ __forceinline__ uint32_t smem_u32(const void* p) {
    uint32_t a;
    asm("{ .reg .u64 t; cvta.to.shared.u64 t, %1; cvt.u32.u64 %0, t; }" : "=r"(a) : "l"(p));
    return a;
}
#if TC5
__device__ __forceinline__ bool elect1() {
    uint32_t r;
    asm volatile("{\n\t.reg .pred p;\n\telect.sync _|p, 0xFFFFFFFF;\n\tselp.b32 %0,1,0,p;\n\t}" : "=r"(r));
    return r != 0;
}
__device__ __forceinline__ void mbar_init(uint32_t a, uint32_t cnt) {
    asm volatile("mbarrier.init.shared.b64 [%0], %1;" :: "r"(a), "r"(cnt) : "memory");
}
__device__ __forceinline__ void mbar_wait(uint32_t a, uint32_t ph) {
    asm volatile(
        "{\n\t.reg .pred P;\n\t"
        "LW_%=:\n\t"
        "mbarrier.try_wait.parity.acquire.cta.shared::cta.b64 P, [%0], %1, 0x989680;\n\t"
        "@P bra LD_%=;\n\t"
        "bra LW_%=;\n\t"
        "LD_%=:\n\t}"
        :: "r"(a), "r"(ph) : "memory");
}
__device__ __forceinline__ void tmalloc(uint32_t smem_dst, uint32_t ncols) {
    asm volatile("tcgen05.alloc.cta_group::1.sync.aligned.shared::cta.b32 [%0], %1;"
                 :: "r"(smem_dst), "r"(ncols) : "memory");
}
__device__ __forceinline__ void tmdealloc(uint32_t tmem, uint32_t ncols) {
    asm volatile("tcgen05.relinquish_alloc_permit.cta_group::1.sync.aligned;");
    asm volatile("tcgen05.dealloc.cta_group::1.sync.aligned.b32 %0, %1;" :: "r"(tmem), "r"(ncols));
}
__device__ __forceinline__ void mma_f16_ss(uint32_t d, uint64_t ad, uint64_t bd, uint32_t idesc, uint32_t en) {
    asm volatile(
        "{\n\t.reg .pred p;\n\tsetp.ne.u32 p, %5, 0;\n\t"
        "tcgen05.mma.cta_group::1.kind::f16 [%0], %1, %2, %3, {%4,%4,%4,%4}, p;\n\t}"
        :: "r"(d), "l"(ad), "l"(bd), "r"(idesc), "r"(0u), "r"(en) : "memory");
}
__device__ __forceinline__ void tccommit(uint32_t mbar) {
    asm volatile("tcgen05.commit.cta_group::1.mbarrier::arrive::one.shared::cluster.b64 [%0];"
                 :: "r"(mbar) : "memory");
}
__device__ __forceinline__ void cpa16(uint32_t dst, const void* src) {
    asm volatile("cp.async.cg.shared.global [%0], [%1], 16;" :: "r"(dst), "l"(src) : "memory");
}
__device__ __forceinline__ void ldtm32(uint32_t* r, uint32_t addr) {
    asm volatile(
        "tcgen05.ld.sync.aligned.32x32b.x32.b32 "
        "{%0, %1, %2, %3, %4, %5, %6, %7, "
        " %8, %9, %10, %11, %12, %13, %14, %15, "
        " %16, %17, %18, %19, %20, %21, %22, %23, "
        " %24, %25, %26, %27, %28, %29, %30, %31}, [%32];"
        : "=r"(r[0]),  "=r"(r[1]),  "=r"(r[2]),  "=r"(r[3]),
          "=r"(r[4]),  "=r"(r[5]),  "=r"(r[6]),  "=r"(r[7]),
          "=r"(r[8]),  "=r"(r[9]),  "=r"(r[10]), "=r"(r[11]),
          "=r"(r[12]), "=r"(r[13]), "=r"(r[14]), "=r"(r[15]),
          "=r"(r[16]), "=r"(r[17]), "=r"(r[18]), "=r"(r[19]),
          "=r"(r[20]), "=r"(r[21]), "=r"(r[22]), "=r"(r[23]),
          "=r"(r[24]), "=r"(r[25]), "=r"(r[26]), "=r"(r[27]),
          "=r"(r[28]), "=r"(r[29]), "=r"(r[30]), "=r"(r[31])
        : "r"(addr));
}
#endif
#define SWZ64(o) ((o) ^ (((o) >> 3) & 0x30))
__device__ __forceinline__ uint64_t mk_desc64(uint32_t addr) {
    return ((uint64_t)4 << 61) | ((uint64_t)1 << 46) | ((uint64_t)32 << 32) |
           ((uint64_t)1 << 16) | ((addr >> 4) & 0x3FFF);
}

// ---------------- fused: weight convert + router ----------------
__global__ void k_pre(const float* __restrict__ Wup, const float* __restrict__ Wdown,
                      const float* __restrict__ x, const float* __restrict__ Wr,
                      const float* __restrict__ br) {
    __shared__ float sW[NE * DIM];
    if (blockIdx.x < NCONV) {
        const size_t HALF = (size_t)NE * HID * DIM;
        size_t base = ((size_t)blockIdx.x * 256 + threadIdx.x) * 8;
        const float* src;
        __half* dst;
        size_t off;
        if (base < HALF) { src = Wup;   dst = g_wup; off = base; }
        else             { src = Wdown; dst = g_wdn; off = base - HALF; }
        float4 v0 = *(const float4*)(src + off);
        float4 v1 = *(const float4*)(src + off + 4);
        __half2 h[4];
        h[0] = __floats2half2_rn(v0.x, v0.y);
        h[1] = __floats2half2_rn(v0.z, v0.w);
        h[2] = __floats2half2_rn(v1.x, v1.y);
        h[3] = __floats2half2_rn(v1.z, v1.w);
        *(int4*)(dst + off) = *(int4*)h;
        return;
    }
    // ---- router blocks ----
    int rb = blockIdx.x - NCONV;        // 0..NTOK/8-1
    for (int i = threadIdx.x; i < NE * DIM; i += 256) sW[i] = Wr[i];
    __syncthreads();

    int warp = threadIdx.x >> 5, lane = threadIdx.x & 31;
    int t = rb * 8 + warp;
    const float4* xr = (const float4*)(x + (size_t)t * DIM);

    float acc[NE];
#pragma unroll
    for (int e = 0; e < NE; e++) acc[e] = 0.f;
#pragma unroll
    for (int p = 0; p < 8; p++) {
        float4 v = xr[p * 32 + lane];
        int c = (p * 32 + lane) * 4;
#pragma unroll
        for (int e = 0; e < NE; e++) {
            const float* w = &sW[e * DIM + c];
            acc[e] += v.x * w[0] + v.y * w[1] + v.z * w[2] + v.w * w[3];
        }
    }
#pragma unroll
    for (int e = 0; e < NE; e++)
#pragma unroll
        for (int o = 16; o; o >>= 1) acc[e] += __shfl_xor_sync(0xffffffffu, acc[e], o);

    if (lane == 0) {
        int best = 0;
        float bv = acc[0] + br[0];
#pragma unroll
        for (int e = 1; e < NE; e++) {
            float v = acc[e] + br[e];
            if (v > bv) { bv = v; best = e; }
        }
        g_expert[t] = best;
        atomicAdd(&g_count[best], 1);
    }
}

// ---------------- init ----------------
__global__ void k_init() {
    int i = threadIdx.x;
    if (i < NE) { g_count[i] = 0; g_cursor[i] = 0; }
}

// ---------------- scan ----------------
__global__ void k_scan() {
    if (threadIdx.x != 0) return;
    int o = 0;
    for (int e = 0; e < NE; e++) { g_off[e] = o; o += g_count[e]; }
    g_off[NE] = o;
    int t = 0;
    for (int e = 0; e < NE; e++) {
        int tiles = (g_count[e] + BM - 1) / BM;
        for (int m = 0; m < tiles; m += GM) {
            g_grp_e[t] = e;
            g_grp_r0[t] = g_off[e] + m * BM;
            int rem = tiles - m;
            g_grp_ng[t] = rem < GM ? rem : GM;
            t++;
        }
    }
    for (; t < MAXG; t++) g_grp_e[t] = -1;
    int tt = 0;
    for (int e = 0; e < NE; e++) {
        int tiles = (g_count[e] + BM - 1) / BM;
        for (int m = 0; m < tiles; m++) { g_tile_e[tt] = e; g_tile_r0[tt] = g_off[e] + m * BM; tt++; }
    }
    for (; tt < MAXT; tt++) g_tile_e[tt] = -1;
}

// ---------------- gather + fp32->fp16 ----------------
__global__ void k_gather(const float* __restrict__ x) {
    int gw = (blockIdx.x * blockDim.x + threadIdx.x) >> 5;
    int lane = threadIdx.x & 31;
    if (gw >= NTOK) return;
    int t = gw, e = g_expert[t];
    int slot = 0;
    if (lane == 0) {
        int r = atomicAdd(&g_cursor[e], 1);
        slot = g_off[e] + r;
        g_perm[slot] = t;
    }
    slot = __shfl_sync(0xffffffffu, slot, 0);
    const float4* src = (const float4*)(x + (size_t)t * DIM);
    __half2* dst = (__half2*)(g_xg + (size_t)slot * DIM);
#pragma unroll
    for (int p = 0; p < 8; p++) {
        float4 v = src[p * 32 + lane];
        dst[(p * 32 + lane) * 2]     = __floats2half2_rn(v.x, v.y);
        dst[(p * 32 + lane) * 2 + 1] = __floats2half2_rn(v.z, v.w);
    }
}

// ================= tcgen05 GEMM: GM=2 x BN=256, 5-buffer lookahead-3 pipeline =================
template<int KTOT, bool UP>
__global__ void __launch_bounds__(256, 1) k_gemm(const float* __restrict__ Wunused,
                                                 const float* __restrict__ bias,
                                                 float* __restrict__ out) {
#if TC5
    extern __shared__ char smem_raw[];
    char* smem = (char*)(((uintptr_t)smem_raw + 1023) & ~(uintptr_t)1023);
    const int NOUT = UP ? HID : DIM;

    int gi = blockIdx.y;
    int e = g_grp_e[gi];
    if (e < 0) return;
    int row0 = g_grp_r0[gi], ng = g_grp_ng[gi], row_end = g_off[e + 1];
    int n0 = blockIdx.x * BN;
    int tid = threadIdx.x, warp = tid >> 5, lane = tid & 31;
    uint32_t sb = smem_u32(smem);

    if (tid == 0) {
#pragma unroll
        for (int j = 0; j < STG; j++) mbar_init(sb + 8 * j, 1);
    }
    if (warp == 0) tmalloc(sb + 64, 512);
    __syncthreads();
    uint32_t tmem;
    asm volatile("ld.shared.b32 %0, [%1];" : "=r"(tmem) : "r"(sb + 64));

    const __half* Asrc = UP ? g_xg : g_h;
    const __half* Ag = Asrc + (size_t)row0 * KTOT;
    const __half* Bg = (UP ? g_wup : g_wdn) + (size_t)e * NOUT * KTOT + (size_t)n0 * KTOT;
    const uint32_t idesc = (1u << 4) | ((BN / 8) << 17) | ((BM / 16) << 24);
    const int SMA = 1024;

    auto LOAD = [&](int s, int buf) {
        uint32_t stBase = sb + SMA + buf * STAGE_BYTES;
#pragma unroll
        for (int g = 0; g < GM; g++) {
            if (g < ng) {
                const __half* As = Ag + (size_t)g * BM * KTOT + s * KC;
                uint32_t ab = stBase + g * 8192;
#pragma unroll
                for (int i = 0; i < 2; i++) {
                    int q = tid + i * 256;
                    int r = q >> 2, c = q & 3;
                    cpa16(ab + SWZ64((uint32_t)(r * 64 + c * 16)),
                          As + (size_t)r * KTOT + c * 8);
                }
            }
        }
        const __half* Bs = Bg + s * KC;
        uint32_t bb = stBase + A_ST;
#pragma unroll
        for (int i = 0; i < 4; i++) {
            int q = tid + i * 256;
            int r = q >> 2, c = q & 3;
            cpa16(bb + SWZ64((uint32_t)(r * 64 + c * 16)),
                  Bs + (size_t)r * KTOT + c * 8);
        }
    };

    const int NKC = KTOT / KC;           // UP: 32, DOWN: 128

#pragma unroll
    for (int p = 0; p < 3; p++) { LOAD(p, p); asm volatile("cp.async.commit_group;" ::: "memory"); }

    for (int s = 0; s < NKC; s++) {
        if (s >= 2) mbar_wait(sb + 8 * ((s - 2) % STG), (uint32_t)(((s - 2) / STG) & 1));
        if (s + 3 < NKC) LOAD(s + 3, (s + 3) % STG);
        asm volatile("cp.async.commit_group;" ::: "memory");
        asm volatile("cp.async.wait_group 3;" ::: "memory");
        asm volatile("fence.proxy.async.shared::cta;" ::: "memory");
        __syncthreads();

        if (warp == 0 && elect1()) {
            uint32_t stBase = sb + SMA + (s % STG) * STAGE_BYTES;
            uint64_t bd = mk_desc64(stBase + A_ST);
#pragma unroll
            for (int g = 0; g < GM; g++) {
                if (g < ng) {
                    uint64_t ad = mk_desc64(stBase + g * 8192);
#pragma unroll
                    for (int ks = 0; ks < 2; ks++) {
                        mma_f16_ss(tmem + g * BN, ad + ks * 2, bd + ks * 2, idesc,
                                   (uint32_t)((s | ks) != 0));
                    }
                }
            }
            tccommit(sb + 8 * (s % STG));
        }
    }
#pragma unroll
    for (int j = 0; j < STG; j++) {
        int sj = (NKC - 1) - ((NKC - 1 - j) % STG);
        mbar_wait(sb + 8 * j, (uint32_t)((sj / STG) & 1));
    }
    asm volatile("tcgen05.fence::after_thread_sync;" ::: "memory");

    // ---- epilogue: 4 warps per group, 8 col-blocks of 32 ----
    int g = warp >> 2;
    int sub = warp & 3;
    const float* bp = bias + (size_t)e * NOUT + n0;
    if (g < ng) {
        int row = row0 + g * BM + sub * 32 + lane;
        bool ok = row < row_end;
#pragma unroll
        for (int cb = 0; cb < 8; cb++) {
            uint32_t r[32];
            ldtm32(r, tmem + g * BN + cb * 32);
            asm volatile("tcgen05.wait::ld.sync.aligned;" ::: "memory");
            if (ok) {
                int col = cb * 32;
                if (UP) {
                    __half2 o[16];
#pragma unroll
                    for (int j = 0; j < 16; j++) {
                        float v0 = __uint_as_float(r[2 * j])     + bp[col + 2 * j];
                        float v1 = __uint_as_float(r[2 * j + 1]) + bp[col + 2 * j + 1];
                        v0 = v0 / (1.f + __expf(-v0));
                        v1 = v1 / (1.f + __expf(-v1));
                        o[j] = __floats2half2_rn(v0, v1);
                    }
                    int4* dst = (int4*)(g_h + (size_t)row * HID + n0 + col);
#pragma unroll
                    for (int q = 0; q < 4; q++) dst[q] = ((int4*)o)[q];
                } else {
                    int tok = g_perm[row];
                    float4* dst = (float4*)(out + (size_t)tok * DIM + n0 + col);
#pragma unroll
                    for (int q = 0; q < 8; q++) {
                        float4 ov;
                        ov.x = __uint_as_float(r[4 * q + 0]) + bp[col + 4 * q + 0];
                        ov.y = __uint_as_float(r[4 * q + 1]) + bp[col + 4 * q + 1];
                        ov.z = __uint_as_float(r[4 * q + 2]) + bp[col + 4 * q + 2];
                        ov.w = __uint_as_float(r[4 * q + 3]) + bp[col + 4 * q + 3];
                        dst[q] = ov;
                    }
                }
            }
        }
    }
    __syncthreads();
    if (warp == 0) tmdealloc(tmem, 512);
#endif
}

// ================= wmma fallback GEMMs (active only in non-'a' image) =================
__global__ __launch_bounds__(256, 2) void k_up(const float* __restrict__ Wup,
                                               const float* __restrict__ bup) {
#if !TC5
    __shared__ __align__(128) char smem_raw[4 * BM * LDSMW * sizeof(__half)];
    __half (*sA)[BM][LDSMW] = (__half (*)[BM][LDSMW])smem_raw;
    __half (*sB)[BM][LDSMW] = (__half (*)[BM][LDSMW])(smem_raw + 2 * BM * LDSMW * sizeof(__half));
    float* stage_all = (float*)smem_raw;

    int mt = blockIdx.y;
    int e = g_tile_e[mt];
    if (e < 0) return;
    int row0 = g_tile_r0[mt], row_end = g_off[e + 1];
    int n0 = blockIdx.x * BNW;
    int tid = threadIdx.x, warp = tid >> 5, lane = tid & 31;
    int wm = warp >> 2, wn = warp & 3;

    const __half* Ag = g_xg + (size_t)row0 * DIM;
    const float*  Bg = Wup + (size_t)e * HID * DIM + (size_t)n0 * DIM;

    wmma::fragment<wmma::accumulator, 16, 16, 16, float> c[4][2];
#pragma unroll
    for (int i = 0; i < 4; i++)
#pragma unroll
        for (int j = 0; j < 2; j++) wmma::fill_fragment(c[i][j], 0.f);

    int4 ra[2];
    float4 rb[4];

    auto LOADA = [&](int kt) {
#pragma unroll
        for (int i = 0; i < 2; i++) {
            int q = tid + i * 256, r = q >> 2, c8 = q & 3;
            ra[i] = *(const int4*)(Ag + (size_t)r * DIM + kt * BK + c8 * 8);
        }
    };
    auto LOADB = [&](int kt) {
#pragma unroll
        for (int i = 0; i < 4; i++) {
            int q = tid + i * 256, r = q >> 3, c4 = q & 7;
            rb[i] = *(const float4*)(Bg + (size_t)r * DIM + kt * BK + c4 * 4);
        }
    };
    auto STORE = [&](int buf) {
#pragma unroll
        for (int i = 0; i < 2; i++) {
            int q = tid + i * 256, r = q >> 2, c8 = q & 3;
            *(int4*)&sA[buf][r][c8 * 8] = ra[i];
        }
#pragma unroll
        for (int i = 0; i < 4; i++) {
            int q = tid + i * 256, r = q >> 3, c4 = q & 7;
            *(__half2*)&sB[buf][r][c4 * 4]     = __floats2half2_rn(rb[i].x, rb[i].y);
            *(__half2*)&sB[buf][r][c4 * 4 + 2] = __floats2half2_rn(rb[i].z, rb[i].w);
        }
    };
    auto COMP = [&](int buf) {
#pragma unroll
        for (int ks = 0; ks < 2; ks++) {
            wmma::fragment<wmma::matrix_a, 16, 16, 16, __half, wmma::row_major> a[4];
            wmma::fragment<wmma::matrix_b, 16, 16, 16, __half, wmma::col_major> b[2];
#pragma unroll
            for (int i = 0; i < 4; i++)
                wmma::load_matrix_sync(a[i], &sA[buf][wm * 64 + i * 16][ks * 16], LDSMW);
#pragma unroll
            for (int j = 0; j < 2; j++)
                wmma::load_matrix_sync(b[j], &sB[buf][wn * 32 + j * 16][ks * 16], LDSMW);
#pragma unroll
            for (int i = 0; i < 4; i++)
#pragma unroll
                for (int j = 0; j < 2; j++)
                    wmma::mma_sync(c[i][j], a[i], b[j], c[i][j]);
        }
    };

    LOADA(0); LOADB(0); STORE(0); __syncthreads();
    const int NK = DIM / BK;
    for (int kt = 1; kt < NK; kt++) {
        LOADA(kt); LOADB(kt);
        COMP((kt - 1) & 1);
        STORE(kt & 1);
        __syncthreads();
    }
    COMP((NK - 1) & 1);
    __syncthreads();

    float* st = stage_all + warp * 16 * 20;
#pragma unroll
    for (int i = 0; i < 4; i++)
#pragma unroll
        for (int j = 0; j < 2; j++) {
            wmma::store_matrix_sync(st, c[i][j], 20, wmma::mem_row_major);
            __syncwarp();
            int rr = lane >> 1, cbase = (lane & 1) * 8;
            int grow = row0 + wm * 64 + i * 16 + rr;
            if (grow < row_end) {
                int gcol = n0 + wn * 32 + j * 16 + cbase;
                __half2 o[4];
#pragma unroll
                for (int k2 = 0; k2 < 4; k2++) {
                    float v0 = st[rr * 20 + cbase + 2 * k2]     + bup[(size_t)e * HID + gcol + 2 * k2];
                    float v1 = st[rr * 20 + cbase + 2 * k2 + 1] + bup[(size_t)e * HID + gcol + 2 * k2 + 1];
                    v0 = v0 / (1.f + expf(-v0));
                    v1 = v1 / (1.f + expf(-v1));
                    o[k2] = __floats2half2_rn(v0, v1);
                }
                *(int4*)&g_h[(size_t)grow * HID + gcol] = *(int4*)o;
            }
            __syncwarp();
        }
#endif
}

__global__ __launch_bounds__(256, 2) void k_down(const float* __restrict__ Wdown,
                                                 const float* __restrict__ bdown,
                                                 float* __restrict__ out) {
#if !TC5
    __shared__ __align__(128) char smem_raw[4 * BM * LDSMW * sizeof(__half)];
    __half (*sA)[BM][LDSMW] = (__half (*)[BM][LDSMW])smem_raw;
    __half (*sB)[BM][LDSMW] = (__half (*)[BM][LDSMW])(smem_raw + 2 * BM * LDSMW * sizeof(__half));
    float* stage_all = (float*)smem_raw;

    int mt = blockIdx.y;
    int e = g_tile_e[mt];
    if (e < 0) return;
    int row0 = g_tile_r0[mt], row_end = g_off[e + 1];
    int n0 = blockIdx.x * BNW;
    int tid = threadIdx.x, warp = tid >> 5, lane = tid & 31;
    int wm = warp >> 2, wn = warp & 3;

    const __half* Ag = g_h + (size_t)row0 * HID;
    const float*  Bg = Wdown + (size_t)e * DIM * HID + (size_t)n0 * HID;

    wmma::fragment<wmma::accumulator, 16, 16, 16, float> c[4][2];
#pragma unroll
    for (int i = 0; i < 4; i++)
#pragma unroll
        for (int j = 0; j < 2; j++) wmma::fill_fragment(c[i][j], 0.f);

    int4 ra[2];
    float4 rb[4];

    auto LOADA = [&](int kt) {
#pragma unroll
        for (int i = 0; i < 2; i++) {
            int q = tid + i * 256, r = q >> 2, c8 = q & 3;
            ra[i] = *(const int4*)(Ag + (size_t)r * HID + kt * BK + c8 * 8);
        }
    };
    auto LOADB = [&](int kt) {
#pragma unroll
        for (int i = 0; i < 4; i++) {
            int q = tid + i * 256, r = q >> 3, c4 = q & 7;
            rb[i] = *(const float4*)(Bg + (size_t)r * HID + kt * BK + c4 * 4);
        }
    };
    auto STORE = [&](int buf) {
#pragma unroll
        for (int i = 0; i < 2; i++) {
            int q = tid + i * 256, r = q >> 2, c8 = q & 3;
            *(int4*)&sA[buf][r][c8 * 8] = ra[i];
        }
#pragma unroll
        for (int i = 0; i < 4; i++) {
            int q = tid + i * 256, r = q >> 3, c4 = q & 7;
            *(__half2*)&sB[buf][r][c4 * 4]     = __floats2half2_rn(rb[i].x, rb[i].y);
            *(__half2*)&sB[buf][r][c4 * 4 + 2] = __floats2half2_rn(rb[i].z, rb[i].w);
        }
    };
    auto COMP = [&](int buf) {
#pragma unroll
        for (int ks = 0; ks < 2; ks++) {
            wmma::fragment<wmma::matrix_a, 16, 16, 16, __half, wmma::row_major> a[4];
            wmma::fragment<wmma::matrix_b, 16, 16, 16, __half, wmma::col_major> b[2];
#pragma unroll
            for (int i = 0; i < 4; i++)
                wmma::load_matrix_sync(a[i], &sA[buf][wm * 64 + i * 16][ks * 16], LDSMW);
#pragma unroll
            for (int j = 0; j < 2; j++)
                wmma::load_matrix_sync(b[j], &sB[buf][wn * 32 + j * 16][ks * 16], LDSMW);
#pragma unroll
            for (int i = 0; i < 4; i++)
#pragma unroll
                for (int j = 0; j < 2; j++)
                    wmma::mma_sync(c[i][j], a[i], b[j], c[i][j]);
        }
    };

    LOADA(0); LOADB(0); STORE(0); __syncthreads();
    const int NK = HID / BK;
    for (int kt = 1; kt < NK; kt++) {
        LOADA(kt); LOADB(kt);
        COMP((kt - 1) & 1);
        STORE(kt & 1);
        __syncthreads();
    }
    COMP((NK - 1) & 1);
    __syncthreads();

    float* st = stage_all + warp * 16 * 20;
#pragma unroll
    for (int i = 0; i < 4; i++)
#pragma unroll
        for (int j = 0; j < 2; j++) {
            wmma::store_matrix_sync(st, c[i][j], 20, wmma::mem_row_major);
            __syncwarp();
            int rr = lane >> 1, cbase = (lane & 1) * 8;
            int grow = row0 + wm * 64 + i * 16 + rr;
            if (grow < row_end) {
                int tok = g_perm[grow];
                int gcol = n0 + wn * 32 + j * 16 + cbase;
                float4 o0, o1;
                o0.x = st[rr * 20 + cbase + 0] + bdown[(size_t)e * DIM + gcol + 0];
                o0.y = st[rr * 20 + cbase + 1] + bdown[(size_t)e * DIM + gcol + 1];
                o0.z = st[rr * 20 + cbase + 2] + bdown[(size_t)e * DIM + gcol + 2];
                o0.w = st[rr * 20 + cbase + 3] + bdown[(size_t)e * DIM + gcol + 3];
                o1.x = st[rr * 20 + cbase + 4] + bdown[(size_t)e * DIM + gcol + 4];
                o1.y = st[rr * 20 + cbase + 5] + bdown[(size_t)e * DIM + gcol + 5];
                o1.z = st[rr * 20 + cbase + 6] + bdown[(size_t)e * DIM + gcol + 6];
                o1.w = st[rr * 20 + cbase + 7] + bdown[(size_t)e * DIM + gcol + 7];
                *(float4*)&out[(size_t)tok * DIM + gcol]     = o0;
                *(float4*)&out[(size_t)tok * DIM + gcol + 4] = o1;
            }
            __syncwarp();
        }
#endif
}

// ---------------- launcher ----------------
extern "C" void kernel_launch(void* const* d_in, const int* in_sizes, int n_in,
                              void* d_out, int out_size) {
    const float* x     = (const float*)d_in[0];
    const float* Wr    = (const float*)d_in[1];
    const float* br    = (const float*)d_in[2];
    const float* Wup   = (const float*)d_in[3];
    const float* bup   = (const float*)d_in[4];
    const float* Wdown = (const float*)d_in[5];
    const float* bdown = (const float*)d_in[6];
    float* out = (float*)d_out;

    cudaFuncSetAttribute(k_gemm<DIM, true>,  cudaFuncAttributeMaxDynamicSharedMemorySize, SMEM_BYTES);
    cudaFuncSetAttribute(k_gemm<HID, false>, cudaFuncAttributeMaxDynamicSharedMemorySize, SMEM_BYTES);

    k_init<<<1, 32>>>();
    k_pre<<<NCONV + NTOK / 8, 256>>>(Wup, Wdown, x, Wr, br);    // convert + router fused
    k_scan<<<1, 1>>>();
    k_gather<<<NTOK / 8, 256>>>(x);
    k_up<<<dim3(HID / BNW, MAXT), 256>>>(Wup, bup);                                     // empty in 'a'
    k_gemm<DIM, true ><<<dim3(HID / BN, MAXG), 256, SMEM_BYTES>>>(Wup, bup, nullptr);
    k_gemm<HID, false><<<dim3(DIM / BN, MAXG), 256, SMEM_BYTES>>>(Wdown, bdown, out);
    k_down<<<dim3(DIM / BNW, MAXT), 256>>>(Wdown, bdown, out);                          // empty in 'a'
}

// round 12
// speedup vs baseline: 2.2133x; 1.0971x over previous
#include <cuda_runtime.h>
#include <cuda.h>
#include <cuda_fp16.h>
#include <mma.h>
#include <stdint.h>
#include <math.h>
#include <dlfcn.h>
#include <string.h>

using namespace nvcuda;

#define NTOK 8192
#define DIM  1024
#define HID  4096
#define NE   8
#define BM   128
#define BN   256
#define GM   2
#define BNW  128
#define BK   32
#define LDSMW (BK + 8)
#define KC   32
#define STG  5
#define A_ST (GM * BM * KC * 2)         // 16384
#define B_ST (BN * KC * 2)              // 16384
#define STAGE_BYTES (A_ST + B_ST)       // 32768
#define PAD  (GM*BM)
#define MAXG (NTOK / BM / GM + NE)      // 40
#define MAXT (NTOK / BM + NE)
#define SMEM_BYTES (1024 + 1024 + STG * STAGE_BYTES)   // 165888

#if defined(__CUDA_ARCH_FEAT_SM103_ALL) || defined(__CUDA_ARCH_FEAT_SM100_ALL) || defined(__CUDA_ARCH_FEAT_SM101_ALL)
#define TC5 1
#else
#define TC5 0
#endif

// ---------------- device scratch ----------------
__device__ int    g_expert[NTOK];
__device__ int    g_count[NE];
__device__ int    g_cursor[NE];
__device__ int    g_off[NE + 1];
__device__ int    g_perm[NTOK];
__device__ int    g_grp_e[MAXG];
__device__ int    g_grp_r0[MAXG];
__device__ int    g_grp_ng[MAXG];
__device__ int    g_tile_e[MAXT];
__device__ int    g_tile_r0[MAXT];
__device__ __half g_xg[(size_t)(NTOK + PAD) * DIM];
__device__ __half g_h [(size_t)(NTOK + PAD) * HID];
__device__ __half g_wup[(size_t)NE * HID * DIM];
__device__ __half g_wdn[(size_t)NE * DIM * HID];

// ---------------- PTX helpers ----------------
__device__ __forceinline__ uint32_t smem_u32(const void* p) {
    uint32_t a;
    asm("{ .reg .u64 t; cvta.to.shared.u64 t, %1; cvt.u32.u64 %0, t; }" : "=r"(a) : "l"(p));
    return a;
}
#if TC5
__device__ __forceinline__ bool elect1() {
    uint32_t r;
    asm volatile("{\n\t.reg .pred p;\n\telect.sync _|p, 0xFFFFFFFF;\n\tselp.b32 %0,1,0,p;\n\t}" : "=r"(r));
    return r != 0;
}
__device__ __forceinline__ void mbar_init(uint32_t a, uint32_t cnt) {
    asm volatile("mbarrier.init.shared.b64 [%0], %1;" :: "r"(a), "r"(cnt) : "memory");
}
__device__ __forceinline__ void mbar_wait(uint32_t a, uint32_t ph) {
    asm volatile(
        "{\n\t.reg .pred P;\n\t"
        "LW_%=:\n\t"
        "mbarrier.try_wait.parity.acquire.cta.shared::cta.b64 P, [%0], %1, 0x989680;\n\t"
        "@P bra LD_%=;\n\t"
        "bra LW_%=;\n\t"
        "LD_%=:\n\t}"
        :: "r"(a), "r"(ph) : "memory");
}
__device__ __forceinline__ void mbar_expect(uint32_t a, uint32_t bytes) {
    asm volatile("mbarrier.arrive.expect_tx.shared.b64 _, [%0], %1;"
                 :: "r"(a), "r"(bytes) : "memory");
}
__device__ __forceinline__ void tma2d(uint32_t dst, const void* map, int x, int y, uint32_t mbar) {
    asm volatile(
        "cp.async.bulk.tensor.2d.shared::cta.global.tile.mbarrier::complete_tx::bytes "
        "[%0], [%1, {%2, %3}], [%4];"
        :: "r"(dst), "l"(map), "r"(x), "r"(y), "r"(mbar) : "memory");
}
__device__ __forceinline__ void tmalloc(uint32_t smem_dst, uint32_t ncols) {
    asm volatile("tcgen05.alloc.cta_group::1.sync.aligned.shared::cta.b32 [%0], %1;"
                 :: "r"(smem_dst), "r"(ncols) : "memory");
}
__device__ __forceinline__ void tmdealloc(uint32_t tmem, uint32_t ncols) {
    asm volatile("tcgen05.relinquish_alloc_permit.cta_group::1.sync.aligned;");
    asm volatile("tcgen05.dealloc.cta_group::1.sync.aligned.b32 %0, %1;" :: "r"(tmem), "r"(ncols));
}
__device__ __forceinline__ void mma_f16_ss(uint32_t d, uint64_t ad, uint64_t bd, uint32_t idesc, uint32_t en) {
    asm volatile(
        "{\n\t.reg .pred p;\n\tsetp.ne.u32 p, %5, 0;\n\t"
        "tcgen05.mma.cta_group::1.kind::f16 [%0], %1, %2, %3, {%4,%4,%4,%4}, p;\n\t}"
        :: "r"(d), "l"(ad), "l"(bd), "r"(idesc), "r"(0u), "r"(en) : "memory");
}
__device__ __forceinline__ void tccommit(uint32_t mbar) {
    asm volatile("tcgen05.commit.cta_group::1.mbarrier::arrive::one.shared::cluster.b64 [%0];"
                 :: "r"(mbar) : "memory");
}
__device__ __forceinline__ void ldtm32(uint32_t* r, uint32_t addr) {
    asm volatile(
        "tcgen05.ld.sync.aligned.32x32b.x32.b32 "
        "{%0, %1, %2, %3, %4, %5, %6, %7, "
        " %8, %9, %10, %11, %12, %13, %14, %15, "
        " %16, %17, %18, %19, %20, %21, %22, %23, "
        " %24, %25, %26, %27, %28, %29, %30, %31}, [%32];"
        : "=r"(r[0]),  "=r"(r[1]),  "=r"(r[2]),  "=r"(r[3]),
          "=r"(r[4]),  "=r"(r[5]),  "=r"(r[6]),  "=r"(r[7]),
          "=r"(r[8]),  "=r"(r[9]),  "=r"(r[10]), "=r"(r[11]),
          "=r"(r[12]), "=r"(r[13]), "=r"(r[14]), "=r"(r[15]),
          "=r"(r[16]), "=r"(r[17]), "=r"(r[18]), "=r"(r[19]),
          "=r"(r[20]), "=r"(r[21]), "=r"(r[22]), "=r"(r[23]),
          "=r"(r[24]), "=r"(r[25]), "=r"(r[26]), "=r"(r[27]),
          "=r"(r[28]), "=r"(r[29]), "=r"(r[30]), "=r"(r[31])
        : "r"(addr));
}
#endif
// SW64 K-major descriptor: layout=4, SBO=32 (512B = 8 rows x 64B), LBO=1 (16B)
__device__ __forceinline__ uint64_t mk_desc64(uint32_t addr) {
    return ((uint64_t)4 << 61) | ((uint64_t)1 << 46) | ((uint64_t)32 << 32) |
           ((uint64_t)1 << 16) | ((addr >> 4) & 0x3FFF);
}

// ---------------- weight fp32 -> fp16 convert ----------------
__global__ void k_convert(const float* __restrict__ Wup, const float* __restrict__ Wdown) {
    const size_t HALF = (size_t)NE * HID * DIM;
    size_t base = ((size_t)blockIdx.x * 256 + threadIdx.x) * 8;
    const float* src;
    __half* dst;
    size_t off;
    if (base < HALF) { src = Wup;   dst = g_wup; off = base; }
    else             { src = Wdown; dst = g_wdn; off = base - HALF; }
    float4 v0 = *(const float4*)(src + off);
    float4 v1 = *(const float4*)(src + off + 4);
    __half2 h[4];
    h[0] = __floats2half2_rn(v0.x, v0.y);
    h[1] = __floats2half2_rn(v0.z, v0.w);
    h[2] = __floats2half2_rn(v1.x, v1.y);
    h[3] = __floats2half2_rn(v1.z, v1.w);
    *(int4*)(dst + off) = *(int4*)h;
}

// ---------------- init ----------------
__global__ void k_init() {
    int i = threadIdx.x;
    if (i < NE) { g_count[i] = 0; g_cursor[i] = 0; }
}

// ---------------- router ----------------
__global__ void k_router(const float* __restrict__ x,
                         const float* __restrict__ Wr,
                         const float* __restrict__ br) {
    __shared__ float sW[NE * DIM];
    for (int i = threadIdx.x; i < NE * DIM; i += 256) sW[i] = Wr[i];
    __syncthreads();

    int warp = threadIdx.x >> 5, lane = threadIdx.x & 31;
    int t = blockIdx.x * 8 + warp;
    const float4* xr = (const float4*)(x + (size_t)t * DIM);

    float acc[NE];
#pragma unroll
    for (int e = 0; e < NE; e++) acc[e] = 0.f;
#pragma unroll
    for (int p = 0; p < 8; p++) {
        float4 v = xr[p * 32 + lane];
        int c = (p * 32 + lane) * 4;
#pragma unroll
        for (int e = 0; e < NE; e++) {
            const float* w = &sW[e * DIM + c];
            acc[e] += v.x * w[0] + v.y * w[1] + v.z * w[2] + v.w * w[3];
        }
    }
#pragma unroll
    for (int e = 0; e < NE; e++)
#pragma unroll
        for (int o = 16; o; o >>= 1) acc[e] += __shfl_xor_sync(0xffffffffu, acc[e], o);

    if (lane == 0) {
        int best = 0;
        float bv = acc[0] + br[0];
#pragma unroll
        for (int e = 1; e < NE; e++) {
            float v = acc[e] + br[e];
            if (v > bv) { bv = v; best = e; }
        }
        g_expert[t] = best;
        atomicAdd(&g_count[best], 1);
    }
}

// ---------------- scan ----------------
__global__ void k_scan() {
    if (threadIdx.x != 0) return;
    int o = 0;
    for (int e = 0; e < NE; e++) { g_off[e] = o; o += g_count[e]; }
    g_off[NE] = o;
    int t = 0;
    for (int e = 0; e < NE; e++) {
        int tiles = (g_count[e] + BM - 1) / BM;
        for (int m = 0; m < tiles; m += GM) {
            g_grp_e[t] = e;
            g_grp_r0[t] = g_off[e] + m * BM;
            int rem = tiles - m;
            g_grp_ng[t] = rem < GM ? rem : GM;
            t++;
        }
    }
    for (; t < MAXG; t++) g_grp_e[t] = -1;
    int tt = 0;
    for (int e = 0; e < NE; e++) {
        int tiles = (g_count[e] + BM - 1) / BM;
        for (int m = 0; m < tiles; m++) { g_tile_e[tt] = e; g_tile_r0[tt] = g_off[e] + m * BM; tt++; }
    }
    for (; tt < MAXT; tt++) g_tile_e[tt] = -1;
}

// ---------------- gather + fp32->fp16 ----------------
__global__ void k_gather(const float* __restrict__ x) {
    int gw = (blockIdx.x * blockDim.x + threadIdx.x) >> 5;
    int lane = threadIdx.x & 31;
    if (gw >= NTOK) return;
    int t = gw, e = g_expert[t];
    int slot = 0;
    if (lane == 0) {
        int r = atomicAdd(&g_cursor[e], 1);
        slot = g_off[e] + r;
        g_perm[slot] = t;
    }
    slot = __shfl_sync(0xffffffffu, slot, 0);
    const float4* src = (const float4*)(x + (size_t)t * DIM);
    __half2* dst = (__half2*)(g_xg + (size_t)slot * DIM);
#pragma unroll
    for (int p = 0; p < 8; p++) {
        float4 v = src[p * 32 + lane];
        dst[(p * 32 + lane) * 2]     = __floats2half2_rn(v.x, v.y);
        dst[(p * 32 + lane) * 2 + 1] = __floats2half2_rn(v.z, v.w);
    }
}

// ================= TMA tcgen05 GEMM: single control thread, 5-buffer lookahead-3 =================
// mbars: full[j]=sb+8j, done[j]=sb+64+8j, tmem ptr at sb+128
template<int KTOT, bool UP>
__global__ void __launch_bounds__(256, 1) k_gemm(const __grid_constant__ CUtensorMap tmA,
                                                 const __grid_constant__ CUtensorMap tmB,
                                                 const float* __restrict__ bias,
                                                 float* __restrict__ out) {
#if TC5
    extern __shared__ char smem_raw[];
    char* smem = (char*)(((uintptr_t)smem_raw + 1023) & ~(uintptr_t)1023);
    const int NOUT = UP ? HID : DIM;

    int gi = blockIdx.y;
    int e = g_grp_e[gi];
    if (e < 0) return;
    int row0 = g_grp_r0[gi], ng = g_grp_ng[gi], row_end = g_off[e + 1];
    int n0 = blockIdx.x * BN;
    int tid = threadIdx.x, warp = tid >> 5, lane = tid & 31;
    uint32_t sb = smem_u32(smem);

    if (tid == 0) {
#pragma unroll
        for (int j = 0; j < STG; j++) {
            mbar_init(sb + 8 * j, 1);            // full (expect_tx arrival)
            mbar_init(sb + 64 + 8 * j, 1);       // done (commit arrival)
        }
    }
    if (warp == 0) tmalloc(sb + 128, 512);
    __syncthreads();
    uint32_t tmem;
    asm volatile("ld.shared.b32 %0, [%1];" : "=r"(tmem) : "r"(sb + 128));

    const uint32_t idesc = (1u << 4) | ((BN / 8) << 17) | ((BM / 16) << 24);
    const int SMA = 1024;
    const int NKC = KTOT / KC;                   // UP: 32, DOWN: 128
    const int brow0 = e * NOUT + n0;

    if (warp == 0 && elect1()) {
        // prologue: stages 0..2
#pragma unroll
        for (int p = 0; p < 3; p++) {
            uint32_t st = sb + SMA + p * STAGE_BYTES;
            mbar_expect(sb + 8 * p, STAGE_BYTES);
            tma2d(st,        &tmA, p * KC, row0,  sb + 8 * p);
            tma2d(st + A_ST, &tmB, p * KC, brow0, sb + 8 * p);
        }
        for (int s = 0; s < NKC; s++) {
            int slot = s % STG;
            // prefetch stage s+3 (buffer reuse gated at MMA distance 2)
            int t = s + 3;
            if (t < NKC) {
                int sl = t % STG;
                if (t >= STG) mbar_wait(sb + 64 + 8 * sl, (uint32_t)(((t - STG) / STG) & 1));
                uint32_t st = sb + SMA + sl * STAGE_BYTES;
                mbar_expect(sb + 8 * sl, STAGE_BYTES);
                tma2d(st,        &tmA, t * KC, row0,  sb + 8 * sl);
                tma2d(st + A_ST, &tmB, t * KC, brow0, sb + 8 * sl);
            }
            // consume stage s
            mbar_wait(sb + 8 * slot, (uint32_t)((s / STG) & 1));
            uint32_t st = sb + SMA + slot * STAGE_BYTES;
            uint64_t bd = mk_desc64(st + A_ST);
#pragma unroll
            for (int g = 0; g < GM; g++) {
                uint64_t ad = mk_desc64(st + g * 8192);
#pragma unroll
                for (int ks = 0; ks < 2; ks++) {
                    mma_f16_ss(tmem + g * BN, ad + ks * 2, bd + ks * 2, idesc,
                               (uint32_t)((s | ks) != 0));
                }
            }
            tccommit(sb + 64 + 8 * slot);
        }
    }
    __syncthreads();                             // all commits issued before anyone polls phases
#pragma unroll
    for (int j = 0; j < STG; j++) {
        int sj = (NKC - 1) - ((NKC - 1 - j) % STG);
        mbar_wait(sb + 64 + 8 * j, (uint32_t)((sj / STG) & 1));
    }
    asm volatile("tcgen05.fence::after_thread_sync;" ::: "memory");

    // ---- epilogue: 4 warps per group, 8 col-blocks of 32 ----
    int g = warp >> 2;
    int sub = warp & 3;
    const float* bp = bias + (size_t)e * NOUT + n0;
    if (g < ng) {
        int row = row0 + g * BM + sub * 32 + lane;
        bool ok = row < row_end;
#pragma unroll
        for (int cb = 0; cb < 8; cb++) {
            uint32_t r[32];
            ldtm32(r, tmem + g * BN + cb * 32);
            asm volatile("tcgen05.wait::ld.sync.aligned;" ::: "memory");
            if (ok) {
                int col = cb * 32;
                if (UP) {
                    __half2 o[16];
#pragma unroll
                    for (int j = 0; j < 16; j++) {
                        float v0 = __uint_as_float(r[2 * j])     + bp[col + 2 * j];
                        float v1 = __uint_as_float(r[2 * j + 1]) + bp[col + 2 * j + 1];
                        v0 = v0 / (1.f + __expf(-v0));
                        v1 = v1 / (1.f + __expf(-v1));
                        o[j] = __floats2half2_rn(v0, v1);
                    }
                    int4* dst = (int4*)(g_h + (size_t)row * HID + n0 + col);
#pragma unroll
                    for (int q = 0; q < 4; q++) dst[q] = ((int4*)o)[q];
                } else {
                    int tok = g_perm[row];
                    float4* dst = (float4*)(out + (size_t)tok * DIM + n0 + col);
#pragma unroll
                    for (int q = 0; q < 8; q++) {
                        float4 ov;
                        ov.x = __uint_as_float(r[4 * q + 0]) + bp[col + 4 * q + 0];
                        ov.y = __uint_as_float(r[4 * q + 1]) + bp[col + 4 * q + 1];
                        ov.z = __uint_as_float(r[4 * q + 2]) + bp[col + 4 * q + 2];
                        ov.w = __uint_as_float(r[4 * q + 3]) + bp[col + 4 * q + 3];
                        dst[q] = ov;
                    }
                }
            }
        }
    }
    __syncthreads();
    if (warp == 0) tmdealloc(tmem, 512);
#endif
}

// ================= wmma fallback GEMMs (active only in non-'a' image) =================
__global__ __launch_bounds__(256, 2) void k_up(const float* __restrict__ Wup,
                                               const float* __restrict__ bup) {
#if !TC5
    __shared__ __align__(128) char smem_raw[4 * BM * LDSMW * sizeof(__half)];
    __half (*sA)[BM][LDSMW] = (__half (*)[BM][LDSMW])smem_raw;
    __half (*sB)[BM][LDSMW] = (__half (*)[BM][LDSMW])(smem_raw + 2 * BM * LDSMW * sizeof(__half));
    float* stage_all = (float*)smem_raw;

    int mt = blockIdx.y;
    int e = g_tile_e[mt];
    if (e < 0) return;
    int row0 = g_tile_r0[mt], row_end = g_off[e + 1];
    int n0 = blockIdx.x * BNW;
    int tid = threadIdx.x, warp = tid >> 5, lane = tid & 31;
    int wm = warp >> 2, wn = warp & 3;

    const __half* Ag = g_xg + (size_t)row0 * DIM;
    const float*  Bg = Wup + (size_t)e * HID * DIM + (size_t)n0 * DIM;

    wmma::fragment<wmma::accumulator, 16, 16, 16, float> c[4][2];
#pragma unroll
    for (int i = 0; i < 4; i++)
#pragma unroll
        for (int j = 0; j < 2; j++) wmma::fill_fragment(c[i][j], 0.f);

    int4 ra[2];
    float4 rb[4];

    auto LOADA = [&](int kt) {
#pragma unroll
        for (int i = 0; i < 2; i++) {
            int q = tid + i * 256, r = q >> 2, c8 = q & 3;
            ra[i] = *(const int4*)(Ag + (size_t)r * DIM + kt * BK + c8 * 8);
        }
    };
    auto LOADB = [&](int kt) {
#pragma unroll
        for (int i = 0; i < 4; i++) {
            int q = tid + i * 256, r = q >> 3, c4 = q & 7;
            rb[i] = *(const float4*)(Bg + (size_t)r * DIM + kt * BK + c4 * 4);
        }
    };
    auto STORE = [&](int buf) {
#pragma unroll
        for (int i = 0; i < 2; i++) {
            int q = tid + i * 256, r = q >> 2, c8 = q & 3;
            *(int4*)&sA[buf][r][c8 * 8] = ra[i];
        }
#pragma unroll
        for (int i = 0; i < 4; i++) {
            int q = tid + i * 256, r = q >> 3, c4 = q & 7;
            *(__half2*)&sB[buf][r][c4 * 4]     = __floats2half2_rn(rb[i].x, rb[i].y);
            *(__half2*)&sB[buf][r][c4 * 4 + 2] = __floats2half2_rn(rb[i].z, rb[i].w);
        }
    };
    auto COMP = [&](int buf) {
#pragma unroll
        for (int ks = 0; ks < 2; ks++) {
            wmma::fragment<wmma::matrix_a, 16, 16, 16, __half, wmma::row_major> a[4];
            wmma::fragment<wmma::matrix_b, 16, 16, 16, __half, wmma::col_major> b[2];
#pragma unroll
            for (int i = 0; i < 4; i++)
                wmma::load_matrix_sync(a[i], &sA[buf][wm * 64 + i * 16][ks * 16], LDSMW);
#pragma unroll
            for (int j = 0; j < 2; j++)
                wmma::load_matrix_sync(b[j], &sB[buf][wn * 32 + j * 16][ks * 16], LDSMW);
#pragma unroll
            for (int i = 0; i < 4; i++)
#pragma unroll
                for (int j = 0; j < 2; j++)
                    wmma::mma_sync(c[i][j], a[i], b[j], c[i][j]);
        }
    };

    LOADA(0); LOADB(0); STORE(0); __syncthreads();
    const int NK = DIM / BK;
    for (int kt = 1; kt < NK; kt++) {
        LOADA(kt); LOADB(kt);
        COMP((kt - 1) & 1);
        STORE(kt & 1);
        __syncthreads();
    }
    COMP((NK - 1) & 1);
    __syncthreads();

    float* st = stage_all + warp * 16 * 20;
#pragma unroll
    for (int i = 0; i < 4; i++)
#pragma unroll
        for (int j = 0; j < 2; j++) {
            wmma::store_matrix_sync(st, c[i][j], 20, wmma::mem_row_major);
            __syncwarp();
            int rr = lane >> 1, cbase = (lane & 1) * 8;
            int grow = row0 + wm * 64 + i * 16 + rr;
            if (grow < row_end) {
                int gcol = n0 + wn * 32 + j * 16 + cbase;
                __half2 o[4];
#pragma unroll
                for (int k2 = 0; k2 < 4; k2++) {
                    float v0 = st[rr * 20 + cbase + 2 * k2]     + bup[(size_t)e * HID + gcol + 2 * k2];
                    float v1 = st[rr * 20 + cbase + 2 * k2 + 1] + bup[(size_t)e * HID + gcol + 2 * k2 + 1];
                    v0 = v0 / (1.f + expf(-v0));
                    v1 = v1 / (1.f + expf(-v1));
                    o[k2] = __floats2half2_rn(v0, v1);
                }
                *(int4*)&g_h[(size_t)grow * HID + gcol] = *(int4*)o;
            }
            __syncwarp();
        }
#endif
}

__global__ __launch_bounds__(256, 2) void k_down(const float* __restrict__ Wdown,
                                                 const float* __restrict__ bdown,
                                                 float* __restrict__ out) {
#if !TC5
    __shared__ __align__(128) char smem_raw[4 * BM * LDSMW * sizeof(__half)];
    __half (*sA)[BM][LDSMW] = (__half (*)[BM][LDSMW])smem_raw;
    __half (*sB)[BM][LDSMW] = (__half (*)[BM][LDSMW])(smem_raw + 2 * BM * LDSMW * sizeof(__half));
    float* stage_all = (float*)smem_raw;

    int mt = blockIdx.y;
    int e = g_tile_e[mt];
    if (e < 0) return;
    int row0 = g_tile_r0[mt], row_end = g_off[e + 1];
    int n0 = blockIdx.x * BNW;
    int tid = threadIdx.x, warp = tid >> 5, lane = tid & 31;
    int wm = warp >> 2, wn = warp & 3;

    const __half* Ag = g_h + (size_t)row0 * HID;
    const float*  Bg = Wdown + (size_t)e * DIM * HID + (size_t)n0 * HID;

    wmma::fragment<wmma::accumulator, 16, 16, 16, float> c[4][2];
#pragma unroll
    for (int i = 0; i < 4; i++)
#pragma unroll
        for (int j = 0; j < 2; j++) wmma::fill_fragment(c[i][j], 0.f);

    int4 ra[2];
    float4 rb[4];

    auto LOADA = [&](int kt) {
#pragma unroll
        for (int i = 0; i < 2; i++) {
            int q = tid + i * 256, r = q >> 2, c8 = q & 3;
            ra[i] = *(const int4*)(Ag + (size_t)r * HID + kt * BK + c8 * 8);
        }
    };
    auto LOADB = [&](int kt) {
#pragma unroll
        for (int i = 0; i < 4; i++) {
            int q = tid + i * 256, r = q >> 3, c4 = q & 7;
            rb[i] = *(const float4*)(Bg + (size_t)r * HID + kt * BK + c4 * 4);
        }
    };
    auto STORE = [&](int buf) {
#pragma unroll
        for (int i = 0; i < 2; i++) {
            int q = tid + i * 256, r = q >> 2, c8 = q & 3;
            *(int4*)&sA[buf][r][c8 * 8] = ra[i];
        }
#pragma unroll
        for (int i = 0; i < 4; i++) {
            int q = tid + i * 256, r = q >> 3, c4 = q & 7;
            *(__half2*)&sB[buf][r][c4 * 4]     = __floats2half2_rn(rb[i].x, rb[i].y);
            *(__half2*)&sB[buf][r][c4 * 4 + 2] = __floats2half2_rn(rb[i].z, rb[i].w);
        }
    };
    auto COMP = [&](int buf) {
#pragma unroll
        for (int ks = 0; ks < 2; ks++) {
            wmma::fragment<wmma::matrix_a, 16, 16, 16, __half, wmma::row_major> a[4];
            wmma::fragment<wmma::matrix_b, 16, 16, 16, __half, wmma::col_major> b[2];
#pragma unroll
            for (int i = 0; i < 4; i++)
                wmma::load_matrix_sync(a[i], &sA[buf][wm * 64 + i * 16][ks * 16], LDSMW);
#pragma unroll
            for (int j = 0; j < 2; j++)
                wmma::load_matrix_sync(b[j], &sB[buf][wn * 32 + j * 16][ks * 16], LDSMW);
#pragma unroll
            for (int i = 0; i < 4; i++)
#pragma unroll
                for (int j = 0; j < 2; j++)
                    wmma::mma_sync(c[i][j], a[i], b[j], c[i][j]);
        }
    };

    LOADA(0); LOADB(0); STORE(0); __syncthreads();
    const int NK = HID / BK;
    for (int kt = 1; kt < NK; kt++) {
        LOADA(kt); LOADB(kt);
        COMP((kt - 1) & 1);
        STORE(kt & 1);
        __syncthreads();
    }
    COMP((NK - 1) & 1);
    __syncthreads();

    float* st = stage_all + warp * 16 * 20;
#pragma unroll
    for (int i = 0; i < 4; i++)
#pragma unroll
        for (int j = 0; j < 2; j++) {
            wmma::store_matrix_sync(st, c[i][j], 20, wmma::mem_row_major);
            __syncwarp();
            int rr = lane >> 1, cbase = (lane & 1) * 8;
            int grow = row0 + wm * 64 + i * 16 + rr;
            if (grow < row_end) {
                int tok = g_perm[grow];
                int gcol = n0 + wn * 32 + j * 16 + cbase;
                float4 o0, o1;
                o0.x = st[rr * 20 + cbase + 0] + bdown[(size_t)e * DIM + gcol + 0];
                o0.y = st[rr * 20 + cbase + 1] + bdown[(size_t)e * DIM + gcol + 1];
                o0.z = st[rr * 20 + cbase + 2] + bdown[(size_t)e * DIM + gcol + 2];
                o0.w = st[rr * 20 + cbase + 3] + bdown[(size_t)e * DIM + gcol + 3];
                o1.x = st[rr * 20 + cbase + 4] + bdown[(size_t)e * DIM + gcol + 4];
                o1.y = st[rr * 20 + cbase + 5] + bdown[(size_t)e * DIM + gcol + 5];
                o1.z = st[rr * 20 + cbase + 6] + bdown[(size_t)e * DIM + gcol + 6];
                o1.w = st[rr * 20 + cbase + 7] + bdown[(size_t)e * DIM + gcol + 7];
                *(float4*)&out[(size_t)tok * DIM + gcol]     = o0;
                *(float4*)&out[(size_t)tok * DIM + gcol + 4] = o1;
            }
            __syncwarp();
        }
#endif
}

// ---------------- host: tensormap encode via dlopen (no -lcuda link dep) ----------------
typedef CUresult (*encode_fn_t)(CUtensorMap*, CUtensorMapDataType, cuuint32_t, void*,
                                const cuuint64_t*, const cuuint64_t*, const cuuint32_t*,
                                const cuuint32_t*, CUtensorMapInterleave, CUtensorMapSwizzle,
                                CUtensorMapL2promotion, CUtensorMapFloatOOBfill);

static void encode_map(encode_fn_t fn, CUtensorMap* m, void* base,
                       uint64_t d0, uint64_t d1) {
    cuuint64_t dims[2]    = {d0, d1};
    cuuint64_t strides[1] = {d0 * 2};           // bytes
    cuuint32_t box[2]     = {KC, 256};          // 32 halves (64B) x 256 rows
    cuuint32_t es[2]      = {1, 1};
    fn(m, CU_TENSOR_MAP_DATA_TYPE_UINT16, 2, base, dims, strides, box, es,
       CU_TENSOR_MAP_INTERLEAVE_NONE, CU_TENSOR_MAP_SWIZZLE_64B,
       CU_TENSOR_MAP_L2_PROMOTION_L2_128B, CU_TENSOR_MAP_FLOAT_OOB_FILL_NONE);
}

// ---------------- launcher ----------------
extern "C" void kernel_launch(void* const* d_in, const int* in_sizes, int n_in,
                              void* d_out, int out_size) {
    const float* x     = (const float*)d_in[0];
    const float* Wr    = (const float*)d_in[1];
    const float* br    = (const float*)d_in[2];
    const float* Wup   = (const float*)d_in[3];
    const float* bup   = (const float*)d_in[4];
    const float* Wdown = (const float*)d_in[5];
    const float* bdown = (const float*)d_in[6];
    float* out = (float*)d_out;

    // resolve cuTensorMapEncodeTiled without link-time libcuda dependency
    void* h = dlopen("libcuda.so.1", RTLD_LAZY | RTLD_NOLOAD);
    if (!h) h = dlopen("libcuda.so.1", RTLD_LAZY);
    if (!h) h = dlopen("libcuda.so", RTLD_LAZY);
    encode_fn_t enc = h ? (encode_fn_t)dlsym(h, "cuTensorMapEncodeTiled") : nullptr;

    void *p_xg = nullptr, *p_h = nullptr, *p_wup = nullptr, *p_wdn = nullptr;
    cudaGetSymbolAddress(&p_xg,  g_xg);
    cudaGetSymbolAddress(&p_h,   g_h);
    cudaGetSymbolAddress(&p_wup, g_wup);
    cudaGetSymbolAddress(&p_wdn, g_wdn);

    CUtensorMap tmA_up, tmB_up, tmA_dn, tmB_dn;
    memset(&tmA_up, 0, sizeof(tmA_up));
    memset(&tmB_up, 0, sizeof(tmB_up));
    memset(&tmA_dn, 0, sizeof(tmA_dn));
    memset(&tmB_dn, 0, sizeof(tmB_dn));
    if (enc) {
        encode_map(enc, &tmA_up, p_xg,  DIM, NTOK + PAD);
        encode_map(enc, &tmB_up, p_wup, DIM, (uint64_t)NE * HID);
        encode_map(enc, &tmA_dn, p_h,   HID, NTOK + PAD);
        encode_map(enc, &tmB_dn, p_wdn, HID, (uint64_t)NE * DIM);
    }

    cudaFuncSetAttribute(k_gemm<DIM, true>,  cudaFuncAttributeMaxDynamicSharedMemorySize, SMEM_BYTES);
    cudaFuncSetAttribute(k_gemm<HID, false>, cudaFuncAttributeMaxDynamicSharedMemorySize, SMEM_BYTES);

    const size_t TOTW = 2 * (size_t)NE * HID * DIM;
    k_convert<<<(int)(TOTW / 2048), 256>>>(Wup, Wdown);
    k_init<<<1, 32>>>();
    k_router<<<NTOK / 8, 256>>>(x, Wr, br);
    k_scan<<<1, 1>>>();
    k_gather<<<NTOK / 8, 256>>>(x);
    k_up<<<dim3(HID / BNW, MAXT), 256>>>(Wup, bup);                                     // empty in 'a'
    k_gemm<DIM, true ><<<dim3(HID / BN, MAXG), 256, SMEM_BYTES>>>(tmA_up, tmB_up, bup, nullptr);
    k_gemm<HID, false><<<dim3(DIM / BN, MAXG), 256, SMEM_BYTES>>>(tmA_dn, tmB_dn, bdown, out);
    k_down<<<dim3(DIM / BNW, MAXT), 256>>>(Wdown, bdown, out);                          // empty in 'a'
}

// round 13
// speedup vs baseline: 2.2852x; 1.0325x over previous
#include <cuda_runtime.h>
#include <cuda.h>
#include <cuda_fp16.h>
#include <mma.h>
#include <stdint.h>
#include <math.h>
#include <dlfcn.h>
#include <string.h>

using namespace nvcuda;

#define NTOK 8192
#define DIM  1024
#define HID  4096
#define NE   8
#define BM   128
#define BN   256
#define GM   2
#define BNW  128
#define BK   32
#define LDSMW (BK + 8)
#define KC   32
#define STG  5
#define A_ST (GM * BM * KC * 2)         // 16384
#define B_ST (BN * KC * 2)              // 16384
#define STAGE_BYTES (A_ST + B_ST)       // 32768
#define PAD  (GM*BM)
#define MAXG (NTOK / BM / GM + NE)      // 40
#define MAXT (NTOK / BM + NE)
#define SMEM_BYTES (1024 + 1024 + STG * STAGE_BYTES)   // 165888
#define WTOT ((size_t)NE * HID * DIM)   // 33554432 per weight tensor
#define NCONV_UP 16384                  // Wup convert blocks (WTOT / 2048)
#define SLICE 52432                     // Wdown elems per UP-GEMM CTA (8-aligned, 640*SLICE >= WTOT)
#define SLICE8 (SLICE / 8)              // 6554

#if defined(__CUDA_ARCH_FEAT_SM103_ALL) || defined(__CUDA_ARCH_FEAT_SM100_ALL) || defined(__CUDA_ARCH_FEAT_SM101_ALL)
#define TC5 1
#else
#define TC5 0
#endif

// ---------------- device scratch ----------------
__device__ int    g_expert[NTOK];
__device__ int    g_count[NE];
__device__ int    g_cursor[NE];
__device__ int    g_off[NE + 1];
__device__ int    g_perm[NTOK];
__device__ int    g_grp_e[MAXG];
__device__ int    g_grp_r0[MAXG];
__device__ int    g_grp_ng[MAXG];
__device__ int    g_tile_e[MAXT];
__device__ int    g_tile_r0[MAXT];
__device__ __half g_xg[(size_t)(NTOK + PAD) * DIM];
__device__ __half g_h [(size_t)(NTOK + PAD) * HID];
__device__ __half g_wup[WTOT];
__device__ __half g_wdn[WTOT];

// ---------------- PTX helpers ----------------
__device__ __forceinline__ uint32_t smem_u32(const void* p) {
    uint32_t a;
    asm("{ .reg .u64 t; cvta.to.shared.u64 t, %1; cvt.u32.u64 %0, t; }" : "=r"(a) : "l"(p));
    return a;
}
#if TC5
__device__ __forceinline__ bool elect1() {
    uint32_t r;
    asm volatile("{\n\t.reg .pred p;\n\telect.sync _|p, 0xFFFFFFFF;\n\tselp.b32 %0,1,0,p;\n\t}" : "=r"(r));
    return r != 0;
}
__device__ __forceinline__ void mbar_init(uint32_t a, uint32_t cnt) {
    asm volatile("mbarrier.init.shared.b64 [%0], %1;" :: "r"(a), "r"(cnt) : "memory");
}
__device__ __forceinline__ void mbar_wait(uint32_t a, uint32_t ph) {
    asm volatile(
        "{\n\t.reg .pred P;\n\t"
        "LW_%=:\n\t"
        "mbarrier.try_wait.parity.acquire.cta.shared::cta.b64 P, [%0], %1, 0x989680;\n\t"
        "@P bra LD_%=;\n\t"
        "bra LW_%=;\n\t"
        "LD_%=:\n\t}"
        :: "r"(a), "r"(ph) : "memory");
}
__device__ __forceinline__ void mbar_expect(uint32_t a, uint32_t bytes) {
    asm volatile("mbarrier.arrive.expect_tx.shared.b64 _, [%0], %1;"
                 :: "r"(a), "r"(bytes) : "memory");
}
__device__ __forceinline__ void tma2d(uint32_t dst, const void* map, int x, int y, uint32_t mbar) {
    asm volatile(
        "cp.async.bulk.tensor.2d.shared::cta.global.tile.mbarrier::complete_tx::bytes "
        "[%0], [%1, {%2, %3}], [%4];"
        :: "r"(dst), "l"(map), "r"(x), "r"(y), "r"(mbar) : "memory");
}
__device__ __forceinline__ void tmalloc(uint32_t smem_dst, uint32_t ncols) {
    asm volatile("tcgen05.alloc.cta_group::1.sync.aligned.shared::cta.b32 [%0], %1;"
                 :: "r"(smem_dst), "r"(ncols) : "memory");
}
__device__ __forceinline__ void tmdealloc(uint32_t tmem, uint32_t ncols) {
    asm volatile("tcgen05.relinquish_alloc_permit.cta_group::1.sync.aligned;");
    asm volatile("tcgen05.dealloc.cta_group::1.sync.aligned.b32 %0, %1;" :: "r"(tmem), "r"(ncols));
}
__device__ __forceinline__ void mma_f16_ss(uint32_t d, uint64_t ad, uint64_t bd, uint32_t idesc, uint32_t en) {
    asm volatile(
        "{\n\t.reg .pred p;\n\tsetp.ne.u32 p, %5, 0;\n\t"
        "tcgen05.mma.cta_group::1.kind::f16 [%0], %1, %2, %3, {%4,%4,%4,%4}, p;\n\t}"
        :: "r"(d), "l"(ad), "l"(bd), "r"(idesc), "r"(0u), "r"(en) : "memory");
}
__device__ __forceinline__ void tccommit(uint32_t mbar) {
    asm volatile("tcgen05.commit.cta_group::1.mbarrier::arrive::one.shared::cluster.b64 [%0];"
                 :: "r"(mbar) : "memory");
}
__device__ __forceinline__ void ldtm32(uint32_t* r, uint32_t addr) {
    asm volatile(
        "tcgen05.ld.sync.aligned.32x32b.x32.b32 "
        "{%0, %1, %2, %3, %4, %5, %6, %7, "
        " %8, %9, %10, %11, %12, %13, %14, %15, "
        " %16, %17, %18, %19, %20, %21, %22, %23, "
        " %24, %25, %26, %27, %28, %29, %30, %31}, [%32];"
        : "=r"(r[0]),  "=r"(r[1]),  "=r"(r[2]),  "=r"(r[3]),
          "=r"(r[4]),  "=r"(r[5]),  "=r"(r[6]),  "=r"(r[7]),
          "=r"(r[8]),  "=r"(r[9]),  "=r"(r[10]), "=r"(r[11]),
          "=r"(r[12]), "=r"(r[13]), "=r"(r[14]), "=r"(r[15]),
          "=r"(r[16]), "=r"(r[17]), "=r"(r[18]), "=r"(r[19]),
          "=r"(r[20]), "=r"(r[21]), "=r"(r[22]), "=r"(r[23]),
          "=r"(r[24]), "=r"(r[25]), "=r"(r[26]), "=r"(r[27]),
          "=r"(r[28]), "=r"(r[29]), "=r"(r[30]), "=r"(r[31])
        : "r"(addr));
}
#endif
// SW64 K-major descriptor: layout=4, SBO=32, LBO=1
__device__ __forceinline__ uint64_t mk_desc64(uint32_t addr) {
    return ((uint64_t)4 << 61) | ((uint64_t)1 << 46) | ((uint64_t)32 << 32) |
           ((uint64_t)1 << 16) | ((addr >> 4) & 0x3FFF);
}

__device__ __forceinline__ void cvt8(const float* src, __half* dst, size_t off) {
    float4 v0 = *(const float4*)(src + off);
    float4 v1 = *(const float4*)(src + off + 4);
    __half2 h[4];
    h[0] = __floats2half2_rn(v0.x, v0.y);
    h[1] = __floats2half2_rn(v0.z, v0.w);
    h[2] = __floats2half2_rn(v1.x, v1.y);
    h[3] = __floats2half2_rn(v1.z, v1.w);
    *(int4*)(dst + off) = *(int4*)h;
}

// ---------------- init ----------------
__global__ void k_init() {
    int i = threadIdx.x;
    if (i < NE) { g_count[i] = 0; g_cursor[i] = 0; }
}

// ---------------- fused: router (blocks first) + Wup convert ----------------
__global__ void k_preR(const float* __restrict__ Wup, const float* __restrict__ x,
                       const float* __restrict__ Wr, const float* __restrict__ br) {
    __shared__ float sW[NE * DIM];
    if (blockIdx.x >= NTOK / 8) {
        // Wup convert block
        size_t base = ((size_t)(blockIdx.x - NTOK / 8) * 256 + threadIdx.x) * 8;
        cvt8(Wup, g_wup, base);
        return;
    }
    // router block
    for (int i = threadIdx.x; i < NE * DIM; i += 256) sW[i] = Wr[i];
    __syncthreads();

    int warp = threadIdx.x >> 5, lane = threadIdx.x & 31;
    int t = blockIdx.x * 8 + warp;
    const float4* xr = (const float4*)(x + (size_t)t * DIM);

    float acc[NE];
#pragma unroll
    for (int e = 0; e < NE; e++) acc[e] = 0.f;
#pragma unroll
    for (int p = 0; p < 8; p++) {
        float4 v = xr[p * 32 + lane];
        int c = (p * 32 + lane) * 4;
#pragma unroll
        for (int e = 0; e < NE; e++) {
            const float* w = &sW[e * DIM + c];
            acc[e] += v.x * w[0] + v.y * w[1] + v.z * w[2] + v.w * w[3];
        }
    }
#pragma unroll
    for (int e = 0; e < NE; e++)
#pragma unroll
        for (int o = 16; o; o >>= 1) acc[e] += __shfl_xor_sync(0xffffffffu, acc[e], o);

    if (lane == 0) {
        int best = 0;
        float bv = acc[0] + br[0];
#pragma unroll
        for (int e = 1; e < NE; e++) {
            float v = acc[e] + br[e];
            if (v > bv) { bv = v; best = e; }
        }
        g_expert[t] = best;
        atomicAdd(&g_count[best], 1);
    }
}

// ---------------- scan ----------------
__global__ void k_scan() {
    if (threadIdx.x != 0) return;
    int o = 0;
    for (int e = 0; e < NE; e++) { g_off[e] = o; o += g_count[e]; }
    g_off[NE] = o;
    int t = 0;
    for (int e = 0; e < NE; e++) {
        int tiles = (g_count[e] + BM - 1) / BM;
        for (int m = 0; m < tiles; m += GM) {
            g_grp_e[t] = e;
            g_grp_r0[t] = g_off[e] + m * BM;
            int rem = tiles - m;
            g_grp_ng[t] = rem < GM ? rem : GM;
            t++;
        }
    }
    for (; t < MAXG; t++) g_grp_e[t] = -1;
    int tt = 0;
    for (int e = 0; e < NE; e++) {
        int tiles = (g_count[e] + BM - 1) / BM;
        for (int m = 0; m < tiles; m++) { g_tile_e[tt] = e; g_tile_r0[tt] = g_off[e] + m * BM; tt++; }
    }
    for (; tt < MAXT; tt++) g_tile_e[tt] = -1;
}

// ---------------- gather + fp32->fp16 ----------------
__global__ void k_gather(const float* __restrict__ x) {
    int gw = (blockIdx.x * blockDim.x + threadIdx.x) >> 5;
    int lane = threadIdx.x & 31;
    if (gw >= NTOK) return;
    int t = gw, e = g_expert[t];
    int slot = 0;
    if (lane == 0) {
        int r = atomicAdd(&g_cursor[e], 1);
        slot = g_off[e] + r;
        g_perm[slot] = t;
    }
    slot = __shfl_sync(0xffffffffu, slot, 0);
    const float4* src = (const float4*)(x + (size_t)t * DIM);
    __half2* dst = (__half2*)(g_xg + (size_t)slot * DIM);
#pragma unroll
    for (int p = 0; p < 8; p++) {
        float4 v = src[p * 32 + lane];
        dst[(p * 32 + lane) * 2]     = __floats2half2_rn(v.x, v.y);
        dst[(p * 32 + lane) * 2 + 1] = __floats2half2_rn(v.z, v.w);
    }
}

// ================= TMA tcgen05 GEMM: control thread + background Wdown convert (UP) =================
// mbars: full[j]=sb+8j, done[j]=sb+64+8j, tmem ptr at sb+128
template<int KTOT, bool UP>
__global__ void __launch_bounds__(256, 1) k_gemm(const __grid_constant__ CUtensorMap tmA,
                                                 const __grid_constant__ CUtensorMap tmB,
                                                 const float* __restrict__ bias,
                                                 float* __restrict__ out,
                                                 const float* __restrict__ wsrc) {
#if TC5
    extern __shared__ char smem_raw[];
    char* smem = (char*)(((uintptr_t)smem_raw + 1023) & ~(uintptr_t)1023);
    const int NOUT = UP ? HID : DIM;

    int gi = blockIdx.y;
    int e = g_grp_e[gi];
    bool active = (e >= 0);
    if (!UP && !active) return;          // DOWN: no background duty
    int row0 = active ? g_grp_r0[gi] : 0;
    int ng   = active ? g_grp_ng[gi] : 0;
    int row_end = active ? g_off[e + 1] : 0;
    int n0 = blockIdx.x * BN;
    int tid = threadIdx.x, warp = tid >> 5, lane = tid & 31;
    uint32_t sb = smem_u32(smem);

    if (active) {
        if (tid == 0) {
#pragma unroll
            for (int j = 0; j < STG; j++) {
                mbar_init(sb + 8 * j, 1);
                mbar_init(sb + 64 + 8 * j, 1);
            }
        }
        if (warp == 0) tmalloc(sb + 128, 512);
    }
    __syncthreads();
    uint32_t tmem = 0;
    if (active)
        asm volatile("ld.shared.b32 %0, [%1];" : "=r"(tmem) : "r"(sb + 128));

    const uint32_t idesc = (1u << 4) | ((BN / 8) << 17) | ((BM / 16) << 24);
    const int SMA = 1024;
    const int NKC = KTOT / KC;
    const int brow0 = e * NOUT + n0;

    // ---- background duty (UP only): warps 1-7 convert this CTA's Wdown slice ----
    if (UP && warp != 0) {
        int cta = blockIdx.y * gridDim.x + blockIdx.x;      // 0..639
        size_t base0 = (size_t)cta * SLICE;
        int wt = tid - 32;                                  // 0..223
#pragma unroll 5
        for (int i = 0; i < 30; i++) {
            int u = i * 224 + wt;
            size_t idx = base0 + (size_t)u * 8;
            if (u < SLICE8 && idx + 8 <= WTOT)
                cvt8(wsrc, g_wdn, idx);
        }
    }

    // ---- control warp: TMA + MMA pipeline ----
    if (active && warp == 0 && elect1()) {
#pragma unroll
        for (int p = 0; p < 3; p++) {
            uint32_t st = sb + SMA + p * STAGE_BYTES;
            mbar_expect(sb + 8 * p, STAGE_BYTES);
            tma2d(st,        &tmA, p * KC, row0,  sb + 8 * p);
            tma2d(st + A_ST, &tmB, p * KC, brow0, sb + 8 * p);
        }
        for (int s = 0; s < NKC; s++) {
            int slot = s % STG;
            int t = s + 3;
            if (t < NKC) {
                int sl = t % STG;
                if (t >= STG) mbar_wait(sb + 64 + 8 * sl, (uint32_t)(((t - STG) / STG) & 1));
                uint32_t st = sb + SMA + sl * STAGE_BYTES;
                mbar_expect(sb + 8 * sl, STAGE_BYTES);
                tma2d(st,        &tmA, t * KC, row0,  sb + 8 * sl);
                tma2d(st + A_ST, &tmB, t * KC, brow0, sb + 8 * sl);
            }
            mbar_wait(sb + 8 * slot, (uint32_t)((s / STG) & 1));
            uint32_t st = sb + SMA + slot * STAGE_BYTES;
            uint64_t bd = mk_desc64(st + A_ST);
#pragma unroll
            for (int g = 0; g < GM; g++) {
                uint64_t ad = mk_desc64(st + g * 8192);
#pragma unroll
                for (int ks = 0; ks < 2; ks++) {
                    mma_f16_ss(tmem + g * BN, ad + ks * 2, bd + ks * 2, idesc,
                               (uint32_t)((s | ks) != 0));
                }
            }
            tccommit(sb + 64 + 8 * slot);
        }
    }
    __syncthreads();
    if (!active) return;                 // UP inactive CTAs: convert done, exit
#pragma unroll
    for (int j = 0; j < STG; j++) {
        int sj = (NKC - 1) - ((NKC - 1 - j) % STG);
        mbar_wait(sb + 64 + 8 * j, (uint32_t)((sj / STG) & 1));
    }
    asm volatile("tcgen05.fence::after_thread_sync;" ::: "memory");

    // ---- epilogue ----
    int g = warp >> 2;
    int sub = warp & 3;
    const float* bp = bias + (size_t)e * NOUT + n0;
    if (g < ng) {
        int row = row0 + g * BM + sub * 32 + lane;
        bool ok = row < row_end;
#pragma unroll
        for (int cb = 0; cb < 8; cb++) {
            uint32_t r[32];
            ldtm32(r, tmem + g * BN + cb * 32);
            asm volatile("tcgen05.wait::ld.sync.aligned;" ::: "memory");
            if (ok) {
                int col = cb * 32;
                if (UP) {
                    __half2 o[16];
#pragma unroll
                    for (int j = 0; j < 16; j++) {
                        float v0 = __uint_as_float(r[2 * j])     + bp[col + 2 * j];
                        float v1 = __uint_as_float(r[2 * j + 1]) + bp[col + 2 * j + 1];
                        v0 = v0 / (1.f + __expf(-v0));
                        v1 = v1 / (1.f + __expf(-v1));
                        o[j] = __floats2half2_rn(v0, v1);
                    }
                    int4* dst = (int4*)(g_h + (size_t)row * HID + n0 + col);
#pragma unroll
                    for (int q = 0; q < 4; q++) dst[q] = ((int4*)o)[q];
                } else {
                    int tok = g_perm[row];
                    float4* dst = (float4*)(out + (size_t)tok * DIM + n0 + col);
#pragma unroll
                    for (int q = 0; q < 8; q++) {
                        float4 ov;
                        ov.x = __uint_as_float(r[4 * q + 0]) + bp[col + 4 * q + 0];
                        ov.y = __uint_as_float(r[4 * q + 1]) + bp[col + 4 * q + 1];
                        ov.z = __uint_as_float(r[4 * q + 2]) + bp[col + 4 * q + 2];
                        ov.w = __uint_as_float(r[4 * q + 3]) + bp[col + 4 * q + 3];
                        dst[q] = ov;
                    }
                }
            }
        }
    }
    __syncthreads();
    if (warp == 0) tmdealloc(tmem, 512);
#endif
}

// ================= wmma fallback GEMMs (active only in non-'a' image) =================
__global__ __launch_bounds__(256, 2) void k_up(const float* __restrict__ Wup,
                                               const float* __restrict__ bup) {
#if !TC5
    __shared__ __align__(128) char smem_raw[4 * BM * LDSMW * sizeof(__half)];
    __half (*sA)[BM][LDSMW] = (__half (*)[BM][LDSMW])smem_raw;
    __half (*sB)[BM][LDSMW] = (__half (*)[BM][LDSMW])(smem_raw + 2 * BM * LDSMW * sizeof(__half));
    float* stage_all = (float*)smem_raw;

    int mt = blockIdx.y;
    int e = g_tile_e[mt];
    if (e < 0) return;
    int row0 = g_tile_r0[mt], row_end = g_off[e + 1];
    int n0 = blockIdx.x * BNW;
    int tid = threadIdx.x, warp = tid >> 5, lane = tid & 31;
    int wm = warp >> 2, wn = warp & 3;

    const __half* Ag = g_xg + (size_t)row0 * DIM;
    const float*  Bg = Wup + (size_t)e * HID * DIM + (size_t)n0 * DIM;

    wmma::fragment<wmma::accumulator, 16, 16, 16, float> c[4][2];
#pragma unroll
    for (int i = 0; i < 4; i++)
#pragma unroll
        for (int j = 0; j < 2; j++) wmma::fill_fragment(c[i][j], 0.f);

    int4 ra[2];
    float4 rb[4];

    auto LOADA = [&](int kt) {
#pragma unroll
        for (int i = 0; i < 2; i++) {
            int q = tid + i * 256, r = q >> 2, c8 = q & 3;
            ra[i] = *(const int4*)(Ag + (size_t)r * DIM + kt * BK + c8 * 8);
        }
    };
    auto LOADB = [&](int kt) {
#pragma unroll
        for (int i = 0; i < 4; i++) {
            int q = tid + i * 256, r = q >> 3, c4 = q & 7;
            rb[i] = *(const float4*)(Bg + (size_t)r * DIM + kt * BK + c4 * 4);
        }
    };
    auto STORE = [&](int buf) {
#pragma unroll
        for (int i = 0; i < 2; i++) {
            int q = tid + i * 256, r = q >> 2, c8 = q & 3;
            *(int4*)&sA[buf][r][c8 * 8] = ra[i];
        }
#pragma unroll
        for (int i = 0; i < 4; i++) {
            int q = tid + i * 256, r = q >> 3, c4 = q & 7;
            *(__half2*)&sB[buf][r][c4 * 4]     = __floats2half2_rn(rb[i].x, rb[i].y);
            *(__half2*)&sB[buf][r][c4 * 4 + 2] = __floats2half2_rn(rb[i].z, rb[i].w);
        }
    };
    auto COMP = [&](int buf) {
#pragma unroll
        for (int ks = 0; ks < 2; ks++) {
            wmma::fragment<wmma::matrix_a, 16, 16, 16, __half, wmma::row_major> a[4];
            wmma::fragment<wmma::matrix_b, 16, 16, 16, __half, wmma::col_major> b[2];
#pragma unroll
            for (int i = 0; i < 4; i++)
                wmma::load_matrix_sync(a[i], &sA[buf][wm * 64 + i * 16][ks * 16], LDSMW);
#pragma unroll
            for (int j = 0; j < 2; j++)
                wmma::load_matrix_sync(b[j], &sB[buf][wn * 32 + j * 16][ks * 16], LDSMW);
#pragma unroll
            for (int i = 0; i < 4; i++)
#pragma unroll
                for (int j = 0; j < 2; j++)
                    wmma::mma_sync(c[i][j], a[i], b[j], c[i][j]);
        }
    };

    LOADA(0); LOADB(0); STORE(0); __syncthreads();
    const int NK = DIM / BK;
    for (int kt = 1; kt < NK; kt++) {
        LOADA(kt); LOADB(kt);
        COMP((kt - 1) & 1);
        STORE(kt & 1);
        __syncthreads();
    }
    COMP((NK - 1) & 1);
    __syncthreads();

    float* st = stage_all + warp * 16 * 20;
#pragma unroll
    for (int i = 0; i < 4; i++)
#pragma unroll
        for (int j = 0; j < 2; j++) {
            wmma::store_matrix_sync(st, c[i][j], 20, wmma::mem_row_major);
            __syncwarp();
            int rr = lane >> 1, cbase = (lane & 1) * 8;
            int grow = row0 + wm * 64 + i * 16 + rr;
            if (grow < row_end) {
                int gcol = n0 + wn * 32 + j * 16 + cbase;
                __half2 o[4];
#pragma unroll
                for (int k2 = 0; k2 < 4; k2++) {
                    float v0 = st[rr * 20 + cbase + 2 * k2]     + bup[(size_t)e * HID + gcol + 2 * k2];
                    float v1 = st[rr * 20 + cbase + 2 * k2 + 1] + bup[(size_t)e * HID + gcol + 2 * k2 + 1];
                    v0 = v0 / (1.f + expf(-v0));
                    v1 = v1 / (1.f + expf(-v1));
                    o[k2] = __floats2half2_rn(v0, v1);
                }
                *(int4*)&g_h[(size_t)grow * HID + gcol] = *(int4*)o;
            }
            __syncwarp();
        }
#endif
}

__global__ __launch_bounds__(256, 2) void k_down(const float* __restrict__ Wdown,
                                                 const float* __restrict__ bdown,
                                                 float* __restrict__ out) {
#if !TC5
    __shared__ __align__(128) char smem_raw[4 * BM * LDSMW * sizeof(__half)];
    __half (*sA)[BM][LDSMW] = (__half (*)[BM][LDSMW])smem_raw;
    __half (*sB)[BM][LDSMW] = (__half (*)[BM][LDSMW])(smem_raw + 2 * BM * LDSMW * sizeof(__half));
    float* stage_all = (float*)smem_raw;

    int mt = blockIdx.y;
    int e = g_tile_e[mt];
    if (e < 0) return;
    int row0 = g_tile_r0[mt], row_end = g_off[e + 1];
    int n0 = blockIdx.x * BNW;
    int tid = threadIdx.x, warp = tid >> 5, lane = tid & 31;
    int wm = warp >> 2, wn = warp & 3;

    const __half* Ag = g_h + (size_t)row0 * HID;
    const float*  Bg = Wdown + (size_t)e * DIM * HID + (size_t)n0 * HID;

    wmma::fragment<wmma::accumulator, 16, 16, 16, float> c[4][2];
#pragma unroll
    for (int i = 0; i < 4; i++)
#pragma unroll
        for (int j = 0; j < 2; j++) wmma::fill_fragment(c[i][j], 0.f);

    int4 ra[2];
    float4 rb[4];

    auto LOADA = [&](int kt) {
#pragma unroll
        for (int i = 0; i < 2; i++) {
            int q = tid + i * 256, r = q >> 2, c8 = q & 3;
            ra[i] = *(const int4*)(Ag + (size_t)r * HID + kt * BK + c8 * 8);
        }
    };
    auto LOADB = [&](int kt) {
#pragma unroll
        for (int i = 0; i < 4; i++) {
            int q = tid + i * 256, r = q >> 3, c4 = q & 7;
            rb[i] = *(const float4*)(Bg + (size_t)r * HID + kt * BK + c4 * 4);
        }
    };
    auto STORE = [&](int buf) {
#pragma unroll
        for (int i = 0; i < 2; i++) {
            int q = tid + i * 256, r = q >> 2, c8 = q & 3;
            *(int4*)&sA[buf][r][c8 * 8] = ra[i];
        }
#pragma unroll
        for (int i = 0; i < 4; i++) {
            int q = tid + i * 256, r = q >> 3, c4 = q & 7;
            *(__half2*)&sB[buf][r][c4 * 4]     = __floats2half2_rn(rb[i].x, rb[i].y);
            *(__half2*)&sB[buf][r][c4 * 4 + 2] = __floats2half2_rn(rb[i].z, rb[i].w);
        }
    };
    auto COMP = [&](int buf) {
#pragma unroll
        for (int ks = 0; ks < 2; ks++) {
            wmma::fragment<wmma::matrix_a, 16, 16, 16, __half, wmma::row_major> a[4];
            wmma::fragment<wmma::matrix_b, 16, 16, 16, __half, wmma::col_major> b[2];
#pragma unroll
            for (int i = 0; i < 4; i++)
                wmma::load_matrix_sync(a[i], &sA[buf][wm * 64 + i * 16][ks * 16], LDSMW);
#pragma unroll
            for (int j = 0; j < 2; j++)
                wmma::load_matrix_sync(b[j], &sB[buf][wn * 32 + j * 16][ks * 16], LDSMW);
#pragma unroll
            for (int i = 0; i < 4; i++)
#pragma unroll
                for (int j = 0; j < 2; j++)
                    wmma::mma_sync(c[i][j], a[i], b[j], c[i][j]);
        }
    };

    LOADA(0); LOADB(0); STORE(0); __syncthreads();
    const int NK = HID / BK;
    for (int kt = 1; kt < NK; kt++) {
        LOADA(kt); LOADB(kt);
        COMP((kt - 1) & 1);
        STORE(kt & 1);
        __syncthreads();
    }
    COMP((NK - 1) & 1);
    __syncthreads();

    float* st = stage_all + warp * 16 * 20;
#pragma unroll
    for (int i = 0; i < 4; i++)
#pragma unroll
        for (int j = 0; j < 2; j++) {
            wmma::store_matrix_sync(st, c[i][j], 20, wmma::mem_row_major);
            __syncwarp();
            int rr = lane >> 1, cbase = (lane & 1) * 8;
            int grow = row0 + wm * 64 + i * 16 + rr;
            if (grow < row_end) {
                int tok = g_perm[grow];
                int gcol = n0 + wn * 32 + j * 16 + cbase;
                float4 o0, o1;
                o0.x = st[rr * 20 + cbase + 0] + bdown[(size_t)e * DIM + gcol + 0];
                o0.y = st[rr * 20 + cbase + 1] + bdown[(size_t)e * DIM + gcol + 1];
                o0.z = st[rr * 20 + cbase + 2] + bdown[(size_t)e * DIM + gcol + 2];
                o0.w = st[rr * 20 + cbase + 3] + bdown[(size_t)e * DIM + gcol + 3];
                o1.x = st[rr * 20 + cbase + 4] + bdown[(size_t)e * DIM + gcol + 4];
                o1.y = st[rr * 20 + cbase + 5] + bdown[(size_t)e * DIM + gcol + 5];
                o1.z = st[rr * 20 + cbase + 6] + bdown[(size_t)e * DIM + gcol + 6];
                o1.w = st[rr * 20 + cbase + 7] + bdown[(size_t)e * DIM + gcol + 7];
                *(float4*)&out[(size_t)tok * DIM + gcol]     = o0;
                *(float4*)&out[(size_t)tok * DIM + gcol + 4] = o1;
            }
            __syncwarp();
        }
#endif
}

// ---------------- host: tensormap encode via dlopen ----------------
typedef CUresult (*encode_fn_t)(CUtensorMap*, CUtensorMapDataType, cuuint32_t, void*,
                                const cuuint64_t*, const cuuint64_t*, const cuuint32_t*,
                                const cuuint32_t*, CUtensorMapInterleave, CUtensorMapSwizzle,
                                CUtensorMapL2promotion, CUtensorMapFloatOOBfill);

static void encode_map(encode_fn_t fn, CUtensorMap* m, void* base,
                       uint64_t d0, uint64_t d1) {
    cuuint64_t dims[2]    = {d0, d1};
    cuuint64_t strides[1] = {d0 * 2};
    cuuint32_t box[2]     = {KC, 256};
    cuuint32_t es[2]      = {1, 1};
    fn(m, CU_TENSOR_MAP_DATA_TYPE_UINT16, 2, base, dims, strides, box, es,
       CU_TENSOR_MAP_INTERLEAVE_NONE, CU_TENSOR_MAP_SWIZZLE_64B,
       CU_TENSOR_MAP_L2_PROMOTION_L2_128B, CU_TENSOR_MAP_FLOAT_OOB_FILL_NONE);
}

// ---------------- launcher ----------------
extern "C" void kernel_launch(void* const* d_in, const int* in_sizes, int n_in,
                              void* d_out, int out_size) {
    const float* x     = (const float*)d_in[0];
    const float* Wr    = (const float*)d_in[1];
    const float* br    = (const float*)d_in[2];
    const float* Wup   = (const float*)d_in[3];
    const float* bup   = (const float*)d_in[4];
    const float* Wdown = (const float*)d_in[5];
    const float* bdown = (const float*)d_in[6];
    float* out = (float*)d_out;

    void* h = dlopen("libcuda.so.1", RTLD_LAZY | RTLD_NOLOAD);
    if (!h) h = dlopen("libcuda.so.1", RTLD_LAZY);
    if (!h) h = dlopen("libcuda.so", RTLD_LAZY);
    encode_fn_t enc = h ? (encode_fn_t)dlsym(h, "cuTensorMapEncodeTiled") : nullptr;

    void *p_xg = nullptr, *p_h = nullptr, *p_wup = nullptr, *p_wdn = nullptr;
    cudaGetSymbolAddress(&p_xg,  g_xg);
    cudaGetSymbolAddress(&p_h,   g_h);
    cudaGetSymbolAddress(&p_wup, g_wup);
    cudaGetSymbolAddress(&p_wdn, g_wdn);

    CUtensorMap tmA_up, tmB_up, tmA_dn, tmB_dn;
    memset(&tmA_up, 0, sizeof(tmA_up));
    memset(&tmB_up, 0, sizeof(tmB_up));
    memset(&tmA_dn, 0, sizeof(tmA_dn));
    memset(&tmB_dn, 0, sizeof(tmB_dn));
    if (enc) {
        encode_map(enc, &tmA_up, p_xg,  DIM, NTOK + PAD);
        encode_map(enc, &tmB_up, p_wup, DIM, (uint64_t)NE * HID);
        encode_map(enc, &tmA_dn, p_h,   HID, NTOK + PAD);
        encode_map(enc, &tmB_dn, p_wdn, HID, (uint64_t)NE * DIM);
    }

    cudaFuncSetAttribute(k_gemm<DIM, true>,  cudaFuncAttributeMaxDynamicSharedMemorySize, SMEM_BYTES);
    cudaFuncSetAttribute(k_gemm<HID, false>, cudaFuncAttributeMaxDynamicSharedMemorySize, SMEM_BYTES);

    k_init<<<1, 32>>>();
    k_preR<<<NTOK / 8 + NCONV_UP, 256>>>(Wup, x, Wr, br);       // router first, Wup convert behind
    k_scan<<<1, 1>>>();
    k_gather<<<NTOK / 8, 256>>>(x);
    k_up<<<dim3(HID / BNW, MAXT), 256>>>(Wup, bup);                                     // empty in 'a'
    k_gemm<DIM, true ><<<dim3(HID / BN, MAXG), 256, SMEM_BYTES>>>(tmA_up, tmB_up, bup, nullptr, Wdown);
    k_gemm<HID, false><<<dim3(DIM / BN, MAXG), 256, SMEM_BYTES>>>(tmA_dn, tmB_dn, bdown, out, nullptr);
    k_down<<<dim3(DIM / BNW, MAXT), 256>>>(Wdown, bdown, out);                          // empty in 'a'
}

// round 14
// speedup vs baseline: 2.2983x; 1.0057x over previous
#include <cuda_runtime.h>
#include <cuda.h>
#include <cuda_fp16.h>
#include <mma.h>
#include <stdint.h>
#include <math.h>
#include <dlfcn.h>
#include <string.h>

using namespace nvcuda;

#define NTOK 8192
#define DIM  1024
#define HID  4096
#define NE   8
#define BM   128
#define BN   256
#define GM   2
#define BNW  128
#define BK   32
#define LDSMW (BK + 8)
#define KC   32
#define STG  5
#define A_ST (GM * BM * KC * 2)         // 16384
#define B_ST (BN * KC * 2)              // 16384
#define STAGE_BYTES (A_ST + B_ST)       // 32768
#define PAD  (GM*BM)
#define MAXG (NTOK / BM / GM + NE)      // 40
#define MAXT (NTOK / BM + NE)
#define SMEM_BYTES (1024 + 1024 + STG * STAGE_BYTES)   // 165888
#define WTOT ((size_t)NE * HID * DIM)   // 33554432 per weight tensor
#define NCONV_UP 16384                  // Wup convert blocks (WTOT / 2048)
#define NRB (NTOK / 8)                  // router blocks = 1024
#define SLICE 52432                     // Wdown elems per UP-GEMM CTA
#define SLICE8 (SLICE / 8)              // 6554

#if defined(__CUDA_ARCH_FEAT_SM103_ALL) || defined(__CUDA_ARCH_FEAT_SM100_ALL) || defined(__CUDA_ARCH_FEAT_SM101_ALL)
#define TC5 1
#else
#define TC5 0
#endif

// ---------------- device scratch ----------------
__device__ int    g_expert[NTOK];
__device__ int    g_count[NE];          // zero-init; scan re-zeroes after consuming
__device__ int    g_cursor[NE];         // zero-init; scan re-zeroes (consumed by prior gather)
__device__ int    g_done;               // router completion ticket; self-resetting
__device__ int    g_off[NE + 1];
__device__ int    g_perm[NTOK];
__device__ int    g_grp_e[MAXG];
__device__ int    g_grp_r0[MAXG];
__device__ int    g_grp_ng[MAXG];
__device__ int    g_tile_e[MAXT];
__device__ int    g_tile_r0[MAXT];
__device__ __half g_xg[(size_t)(NTOK + PAD) * DIM];
__device__ __half g_h [(size_t)(NTOK + PAD) * HID];
__device__ __half g_wup[WTOT];
__device__ __half g_wdn[WTOT];

// ---------------- PTX helpers ----------------
__device__ __forceinline__ uint32_t smem_u32(const void* p) {
    uint32_t a;
    asm("{ .reg .u64 t; cvta.to.shared.u64 t, %1; cvt.u32.u64 %0, t; }" : "=r"(a) : "l"(p));
    return a;
}
#if TC5
__device__ __forceinline__ bool elect1() {
    uint32_t r;
    asm volatile("{\n\t.reg .pred p;\n\telect.sync _|p, 0xFFFFFFFF;\n\tselp.b32 %0,1,0,p;\n\t}" : "=r"(r));
    return r != 0;
}
__device__ __forceinline__ void mbar_init(uint32_t a, uint32_t cnt) {
    asm volatile("mbarrier.init.shared.b64 [%0], %1;" :: "r"(a), "r"(cnt) : "memory");
}
__device__ __forceinline__ void mbar_wait(uint32_t a, uint32_t ph) {
    asm volatile(
        "{\n\t.reg .pred P;\n\t"
        "LW_%=:\n\t"
        "mbarrier.try_wait.parity.acquire.cta.shared::cta.b64 P, [%0], %1, 0x989680;\n\t"
        "@P bra LD_%=;\n\t"
        "bra LW_%=;\n\t"
        "LD_%=:\n\t}"
        :: "r"(a), "r"(ph) : "memory");
}
__device__ __forceinline__ void mbar_expect(uint32_t a, uint32_t bytes) {
    asm volatile("mbarrier.arrive.expect_tx.shared.b64 _, [%0], %1;"
                 :: "r"(a), "r"(bytes) : "memory");
}
__device__ __forceinline__ void tma2d(uint32_t dst, const void* map, int x, int y, uint32_t mbar) {
    asm volatile(
        "cp.async.bulk.tensor.2d.shared::cta.global.tile.mbarrier::complete_tx::bytes "
        "[%0], [%1, {%2, %3}], [%4];"
        :: "r"(dst), "l"(map), "r"(x), "r"(y), "r"(mbar) : "memory");
}
__device__ __forceinline__ void tmalloc(uint32_t smem_dst, uint32_t ncols) {
    asm volatile("tcgen05.alloc.cta_group::1.sync.aligned.shared::cta.b32 [%0], %1;"
                 :: "r"(smem_dst), "r"(ncols) : "memory");
}
__device__ __forceinline__ void tmdealloc(uint32_t tmem, uint32_t ncols) {
    asm volatile("tcgen05.relinquish_alloc_permit.cta_group::1.sync.aligned;");
    asm volatile("tcgen05.dealloc.cta_group::1.sync.aligned.b32 %0, %1;" :: "r"(tmem), "r"(ncols));
}
__device__ __forceinline__ void mma_f16_ss(uint32_t d, uint64_t ad, uint64_t bd, uint32_t idesc, uint32_t en) {
    asm volatile(
        "{\n\t.reg .pred p;\n\tsetp.ne.u32 p, %5, 0;\n\t"
        "tcgen05.mma.cta_group::1.kind::f16 [%0], %1, %2, %3, {%4,%4,%4,%4}, p;\n\t}"
        :: "r"(d), "l"(ad), "l"(bd), "r"(idesc), "r"(0u), "r"(en) : "memory");
}
__device__ __forceinline__ void tccommit(uint32_t mbar) {
    asm volatile("tcgen05.commit.cta_group::1.mbarrier::arrive::one.shared::cluster.b64 [%0];"
                 :: "r"(mbar) : "memory");
}
__device__ __forceinline__ void ldtm32(uint32_t* r, uint32_t addr) {
    asm volatile(
        "tcgen05.ld.sync.aligned.32x32b.x32.b32 "
        "{%0, %1, %2, %3, %4, %5, %6, %7, "
        " %8, %9, %10, %11, %12, %13, %14, %15, "
        " %16, %17, %18, %19, %20, %21, %22, %23, "
        " %24, %25, %26, %27, %28, %29, %30, %31}, [%32];"
        : "=r"(r[0]),  "=r"(r[1]),  "=r"(r[2]),  "=r"(r[3]),
          "=r"(r[4]),  "=r"(r[5]),  "=r"(r[6]),  "=r"(r[7]),
          "=r"(r[8]),  "=r"(r[9]),  "=r"(r[10]), "=r"(r[11]),
          "=r"(r[12]), "=r"(r[13]), "=r"(r[14]), "=r"(r[15]),
          "=r"(r[16]), "=r"(r[17]), "=r"(r[18]), "=r"(r[19]),
          "=r"(r[20]), "=r"(r[21]), "=r"(r[22]), "=r"(r[23]),
          "=r"(r[24]), "=r"(r[25]), "=r"(r[26]), "=r"(r[27]),
          "=r"(r[28]), "=r"(r[29]), "=r"(r[30]), "=r"(r[31])
        : "r"(addr));
}
#endif
// SW64 K-major descriptor: layout=4, SBO=32, LBO=1
__device__ __forceinline__ uint64_t mk_desc64(uint32_t addr) {
    return ((uint64_t)4 << 61) | ((uint64_t)1 << 46) | ((uint64_t)32 << 32) |
           ((uint64_t)1 << 16) | ((addr >> 4) & 0x3FFF);
}

__device__ __forceinline__ void cvt8(const float* src, __half* dst, size_t off) {
    float4 v0 = *(const float4*)(src + off);
    float4 v1 = *(const float4*)(src + off + 4);
    __half2 h[4];
    h[0] = __floats2half2_rn(v0.x, v0.y);
    h[1] = __floats2half2_rn(v0.z, v0.w);
    h[2] = __floats2half2_rn(v1.x, v1.y);
    h[3] = __floats2half2_rn(v1.z, v1.w);
    *(int4*)(dst + off) = *(int4*)h;
}

// ---------------- router + last-block inline scan (self-resetting state) ----------------
__global__ void k_router(const float* __restrict__ x,
                         const float* __restrict__ Wr,
                         const float* __restrict__ br) {
    __shared__ float sW[NE * DIM];
    for (int i = threadIdx.x; i < NE * DIM; i += 256) sW[i] = Wr[i];
    __syncthreads();

    int warp = threadIdx.x >> 5, lane = threadIdx.x & 31;
    int t = blockIdx.x * 8 + warp;
    const float4* xr = (const float4*)(x + (size_t)t * DIM);

    float acc[NE];
#pragma unroll
    for (int e = 0; e < NE; e++) acc[e] = 0.f;
#pragma unroll
    for (int p = 0; p < 8; p++) {
        float4 v = xr[p * 32 + lane];
        int c = (p * 32 + lane) * 4;
#pragma unroll
        for (int e = 0; e < NE; e++) {
            const float* w = &sW[e * DIM + c];
            acc[e] += v.x * w[0] + v.y * w[1] + v.z * w[2] + v.w * w[3];
        }
    }
#pragma unroll
    for (int e = 0; e < NE; e++)
#pragma unroll
        for (int o = 16; o; o >>= 1) acc[e] += __shfl_xor_sync(0xffffffffu, acc[e], o);

    if (lane == 0) {
        int best = 0;
        float bv = acc[0] + br[0];
#pragma unroll
        for (int e = 1; e < NE; e++) {
            float v = acc[e] + br[e];
            if (v > bv) { bv = v; best = e; }
        }
        g_expert[t] = best;
        atomicAdd(&g_count[best], 1);
    }
    __syncthreads();
    if (threadIdx.x == 0) {
        __threadfence();
        int tk = atomicAdd(&g_done, 1);
        if (tk == NRB - 1) {
            // ---- inline scan (last-finishing block; all router writes visible) ----
            int cnt[NE];
            int o = 0;
#pragma unroll
            for (int e = 0; e < NE; e++) {
                cnt[e] = g_count[e];
                g_off[e] = o;
                o += cnt[e];
            }
            g_off[NE] = o;
            int tg = 0;
            for (int e = 0; e < NE; e++) {
                int tiles = (cnt[e] + BM - 1) / BM;
                for (int m = 0; m < tiles; m += GM) {
                    g_grp_e[tg] = e;
                    g_grp_r0[tg] = g_off[e] + m * BM;
                    int rem = tiles - m;
                    g_grp_ng[tg] = rem < GM ? rem : GM;
                    tg++;
                }
            }
            for (; tg < MAXG; tg++) g_grp_e[tg] = -1;
            int tt = 0;
            for (int e = 0; e < NE; e++) {
                int tiles = (cnt[e] + BM - 1) / BM;
                for (int m = 0; m < tiles; m++) {
                    g_tile_e[tt] = e;
                    g_tile_r0[tt] = g_off[e] + m * BM;
                    tt++;
                }
            }
            for (; tt < MAXT; tt++) g_tile_e[tt] = -1;
            // reset consumed state for the next graph replay (deterministic)
#pragma unroll
            for (int e = 0; e < NE; e++) { g_count[e] = 0; g_cursor[e] = 0; }
            g_done = 0;
            __threadfence();
        }
    }
}

// ---------------- gather (blocks 0..NRB-1) + Wup convert (blocks behind) ----------------
__global__ void k_gather(const float* __restrict__ x, const float* __restrict__ Wup) {
    if (blockIdx.x >= NRB) {
        size_t base = ((size_t)(blockIdx.x - NRB) * 256 + threadIdx.x) * 8;
        cvt8(Wup, g_wup, base);
        return;
    }
    int gw = (blockIdx.x * blockDim.x + threadIdx.x) >> 5;
    int lane = threadIdx.x & 31;
    if (gw >= NTOK) return;
    int t = gw, e = g_expert[t];
    int slot = 0;
    if (lane == 0) {
        int r = atomicAdd(&g_cursor[e], 1);
        slot = g_off[e] + r;
        g_perm[slot] = t;
    }
    slot = __shfl_sync(0xffffffffu, slot, 0);
    const float4* src = (const float4*)(x + (size_t)t * DIM);
    __half2* dst = (__half2*)(g_xg + (size_t)slot * DIM);
#pragma unroll
    for (int p = 0; p < 8; p++) {
        float4 v = src[p * 32 + lane];
        dst[(p * 32 + lane) * 2]     = __floats2half2_rn(v.x, v.y);
        dst[(p * 32 + lane) * 2 + 1] = __floats2half2_rn(v.z, v.w);
    }
}

// ================= TMA tcgen05 GEMM: control thread + background Wdown convert (UP) =================
template<int KTOT, bool UP>
__global__ void __launch_bounds__(256, 1) k_gemm(const __grid_constant__ CUtensorMap tmA,
                                                 const __grid_constant__ CUtensorMap tmB,
                                                 const float* __restrict__ bias,
                                                 float* __restrict__ out,
                                                 const float* __restrict__ wsrc) {
#if TC5
    extern __shared__ char smem_raw[];
    char* smem = (char*)(((uintptr_t)smem_raw + 1023) & ~(uintptr_t)1023);
    const int NOUT = UP ? HID : DIM;

    int gi = blockIdx.y;
    int e = g_grp_e[gi];
    bool active = (e >= 0);
    if (!UP && !active) return;
    int row0 = active ? g_grp_r0[gi] : 0;
    int ng   = active ? g_grp_ng[gi] : 0;
    int row_end = active ? g_off[e + 1] : 0;
    int n0 = blockIdx.x * BN;
    int tid = threadIdx.x, warp = tid >> 5, lane = tid & 31;
    uint32_t sb = smem_u32(smem);

    if (active) {
        if (tid == 0) {
#pragma unroll
            for (int j = 0; j < STG; j++) {
                mbar_init(sb + 8 * j, 1);
                mbar_init(sb + 64 + 8 * j, 1);
            }
        }
        if (warp == 0) tmalloc(sb + 128, 512);
    }
    __syncthreads();
    uint32_t tmem = 0;
    if (active)
        asm volatile("ld.shared.b32 %0, [%1];" : "=r"(tmem) : "r"(sb + 128));

    const uint32_t idesc = (1u << 4) | ((BN / 8) << 17) | ((BM / 16) << 24);
    const int SMA = 1024;
    const int NKC = KTOT / KC;
    const int brow0 = e * NOUT + n0;

    // background duty (UP only): warps 1-7 convert this CTA's Wdown slice
    if (UP && warp != 0) {
        int cta = blockIdx.y * gridDim.x + blockIdx.x;
        size_t base0 = (size_t)cta * SLICE;
        int wt = tid - 32;
#pragma unroll 5
        for (int i = 0; i < 30; i++) {
            int u = i * 224 + wt;
            size_t idx = base0 + (size_t)u * 8;
            if (u < SLICE8 && idx + 8 <= WTOT)
                cvt8(wsrc, g_wdn, idx);
        }
    }

    // control warp: TMA + MMA pipeline
    if (active && warp == 0 && elect1()) {
#pragma unroll
        for (int p = 0; p < 3; p++) {
            uint32_t st = sb + SMA + p * STAGE_BYTES;
            mbar_expect(sb + 8 * p, STAGE_BYTES);
            tma2d(st,        &tmA, p * KC, row0,  sb + 8 * p);
            tma2d(st + A_ST, &tmB, p * KC, brow0, sb + 8 * p);
        }
        for (int s = 0; s < NKC; s++) {
            int slot = s % STG;
            int t = s + 3;
            if (t < NKC) {
                int sl = t % STG;
                if (t >= STG) mbar_wait(sb + 64 + 8 * sl, (uint32_t)(((t - STG) / STG) & 1));
                uint32_t st = sb + SMA + sl * STAGE_BYTES;
                mbar_expect(sb + 8 * sl, STAGE_BYTES);
                tma2d(st,        &tmA, t * KC, row0,  sb + 8 * sl);
                tma2d(st + A_ST, &tmB, t * KC, brow0, sb + 8 * sl);
            }
            mbar_wait(sb + 8 * slot, (uint32_t)((s / STG) & 1));
            uint32_t st = sb + SMA + slot * STAGE_BYTES;
            uint64_t bd = mk_desc64(st + A_ST);
#pragma unroll
            for (int g = 0; g < GM; g++) {
                uint64_t ad = mk_desc64(st + g * 8192);
#pragma unroll
                for (int ks = 0; ks < 2; ks++) {
                    mma_f16_ss(tmem + g * BN, ad + ks * 2, bd + ks * 2, idesc,
                               (uint32_t)((s | ks) != 0));
                }
            }
            tccommit(sb + 64 + 8 * slot);
        }
    }
    __syncthreads();
    if (!active) return;
#pragma unroll
    for (int j = 0; j < STG; j++) {
        int sj = (NKC - 1) - ((NKC - 1 - j) % STG);
        mbar_wait(sb + 64 + 8 * j, (uint32_t)((sj / STG) & 1));
    }
    asm volatile("tcgen05.fence::after_thread_sync;" ::: "memory");

    // epilogue
    int g = warp >> 2;
    int sub = warp & 3;
    const float* bp = bias + (size_t)e * NOUT + n0;
    if (g < ng) {
        int row = row0 + g * BM + sub * 32 + lane;
        bool ok = row < row_end;
#pragma unroll
        for (int cb = 0; cb < 8; cb++) {
            uint32_t r[32];
            ldtm32(r, tmem + g * BN + cb * 32);
            asm volatile("tcgen05.wait::ld.sync.aligned;" ::: "memory");
            if (ok) {
                int col = cb * 32;
                if (UP) {
                    __half2 o[16];
#pragma unroll
                    for (int j = 0; j < 16; j++) {
                        float v0 = __uint_as_float(r[2 * j])     + bp[col + 2 * j];
                        float v1 = __uint_as_float(r[2 * j + 1]) + bp[col + 2 * j + 1];
                        v0 = v0 / (1.f + __expf(-v0));
                        v1 = v1 / (1.f + __expf(-v1));
                        o[j] = __floats2half2_rn(v0, v1);
                    }
                    int4* dst = (int4*)(g_h + (size_t)row * HID + n0 + col);
#pragma unroll
                    for (int q = 0; q < 4; q++) dst[q] = ((int4*)o)[q];
                } else {
                    int tok = g_perm[row];
                    float4* dst = (float4*)(out + (size_t)tok * DIM + n0 + col);
#pragma unroll
                    for (int q = 0; q < 8; q++) {
                        float4 ov;
                        ov.x = __uint_as_float(r[4 * q + 0]) + bp[col + 4 * q + 0];
                        ov.y = __uint_as_float(r[4 * q + 1]) + bp[col + 4 * q + 1];
                        ov.z = __uint_as_float(r[4 * q + 2]) + bp[col + 4 * q + 2];
                        ov.w = __uint_as_float(r[4 * q + 3]) + bp[col + 4 * q + 3];
                        dst[q] = ov;
                    }
                }
            }
        }
    }
    __syncthreads();
    if (warp == 0) tmdealloc(tmem, 512);
#endif
}

// ================= wmma fallback GEMMs (active only in non-'a' image) =================
__global__ __launch_bounds__(256, 2) void k_up(const float* __restrict__ Wup,
                                               const float* __restrict__ bup) {
#if !TC5
    __shared__ __align__(128) char smem_raw[4 * BM * LDSMW * sizeof(__half)];
    __half (*sA)[BM][LDSMW] = (__half (*)[BM][LDSMW])smem_raw;
    __half (*sB)[BM][LDSMW] = (__half (*)[BM][LDSMW])(smem_raw + 2 * BM * LDSMW * sizeof(__half));
    float* stage_all = (float*)smem_raw;

    int mt = blockIdx.y;
    int e = g_tile_e[mt];
    if (e < 0) return;
    int row0 = g_tile_r0[mt], row_end = g_off[e + 1];
    int n0 = blockIdx.x * BNW;
    int tid = threadIdx.x, warp = tid >> 5, lane = tid & 31;
    int wm = warp >> 2, wn = warp & 3;

    const __half* Ag = g_xg + (size_t)row0 * DIM;
    const float*  Bg = Wup + (size_t)e * HID * DIM + (size_t)n0 * DIM;

    wmma::fragment<wmma::accumulator, 16, 16, 16, float> c[4][2];
#pragma unroll
    for (int i = 0; i < 4; i++)
#pragma unroll
        for (int j = 0; j < 2; j++) wmma::fill_fragment(c[i][j], 0.f);

    int4 ra[2];
    float4 rb[4];

    auto LOADA = [&](int kt) {
#pragma unroll
        for (int i = 0; i < 2; i++) {
            int q = tid + i * 256, r = q >> 2, c8 = q & 3;
            ra[i] = *(const int4*)(Ag + (size_t)r * DIM + kt * BK + c8 * 8);
        }
    };
    auto LOADB = [&](int kt) {
#pragma unroll
        for (int i = 0; i < 4; i++) {
            int q = tid + i * 256, r = q >> 3, c4 = q & 7;
            rb[i] = *(const float4*)(Bg + (size_t)r * DIM + kt * BK + c4 * 4);
        }
    };
    auto STORE = [&](int buf) {
#pragma unroll
        for (int i = 0; i < 2; i++) {
            int q = tid + i * 256, r = q >> 2, c8 = q & 3;
            *(int4*)&sA[buf][r][c8 * 8] = ra[i];
        }
#pragma unroll
        for (int i = 0; i < 4; i++) {
            int q = tid + i * 256, r = q >> 3, c4 = q & 7;
            *(__half2*)&sB[buf][r][c4 * 4]     = __floats2half2_rn(rb[i].x, rb[i].y);
            *(__half2*)&sB[buf][r][c4 * 4 + 2] = __floats2half2_rn(rb[i].z, rb[i].w);
        }
    };
    auto COMP = [&](int buf) {
#pragma unroll
        for (int ks = 0; ks < 2; ks++) {
            wmma::fragment<wmma::matrix_a, 16, 16, 16, __half, wmma::row_major> a[4];
            wmma::fragment<wmma::matrix_b, 16, 16, 16, __half, wmma::col_major> b[2];
#pragma unroll
            for (int i = 0; i < 4; i++)
                wmma::load_matrix_sync(a[i], &sA[buf][wm * 64 + i * 16][ks * 16], LDSMW);
#pragma unroll
            for (int j = 0; j < 2; j++)
                wmma::load_matrix_sync(b[j], &sB[buf][wn * 32 + j * 16][ks * 16], LDSMW);
#pragma unroll
            for (int i = 0; i < 4; i++)
#pragma unroll
                for (int j = 0; j < 2; j++)
                    wmma::mma_sync(c[i][j], a[i], b[j], c[i][j]);
        }
    };

    LOADA(0); LOADB(0); STORE(0); __syncthreads();
    const int NK = DIM / BK;
    for (int kt = 1; kt < NK; kt++) {
        LOADA(kt); LOADB(kt);
        COMP((kt - 1) & 1);
        STORE(kt & 1);
        __syncthreads();
    }
    COMP((NK - 1) & 1);
    __syncthreads();

    float* st = stage_all + warp * 16 * 20;
#pragma unroll
    for (int i = 0; i < 4; i++)
#pragma unroll
        for (int j = 0; j < 2; j++) {
            wmma::store_matrix_sync(st, c[i][j], 20, wmma::mem_row_major);
            __syncwarp();
            int rr = lane >> 1, cbase = (lane & 1) * 8;
            int grow = row0 + wm * 64 + i * 16 + rr;
            if (grow < row_end) {
                int gcol = n0 + wn * 32 + j * 16 + cbase;
                __half2 o[4];
#pragma unroll
                for (int k2 = 0; k2 < 4; k2++) {
                    float v0 = st[rr * 20 + cbase + 2 * k2]     + bup[(size_t)e * HID + gcol + 2 * k2];
                    float v1 = st[rr * 20 + cbase + 2 * k2 + 1] + bup[(size_t)e * HID + gcol + 2 * k2 + 1];
                    v0 = v0 / (1.f + expf(-v0));
                    v1 = v1 / (1.f + expf(-v1));
                    o[k2] = __floats2half2_rn(v0, v1);
                }
                *(int4*)&g_h[(size_t)grow * HID + gcol] = *(int4*)o;
            }
            __syncwarp();
        }
#endif
}

__global__ __launch_bounds__(256, 2) void k_down(const float* __restrict__ Wdown,
                                                 const float* __restrict__ bdown,
                                                 float* __restrict__ out) {
#if !TC5
    __shared__ __align__(128) char smem_raw[4 * BM * LDSMW * sizeof(__half)];
    __half (*sA)[BM][LDSMW] = (__half (*)[BM][LDSMW])smem_raw;
    __half (*sB)[BM][LDSMW] = (__half (*)[BM][LDSMW])(smem_raw + 2 * BM * LDSMW * sizeof(__half));
    float* stage_all = (float*)smem_raw;

    int mt = blockIdx.y;
    int e = g_tile_e[mt];
    if (e < 0) return;
    int row0 = g_tile_r0[mt], row_end = g_off[e + 1];
    int n0 = blockIdx.x * BNW;
    int tid = threadIdx.x, warp = tid >> 5, lane = tid & 31;
    int wm = warp >> 2, wn = warp & 3;

    const __half* Ag = g_h + (size_t)row0 * HID;
    const float*  Bg = Wdown + (size_t)e * DIM * HID + (size_t)n0 * HID;

    wmma::fragment<wmma::accumulator, 16, 16, 16, float> c[4][2];
#pragma unroll
    for (int i = 0; i < 4; i++)
#pragma unroll
        for (int j = 0; j < 2; j++) wmma::fill_fragment(c[i][j], 0.f);

    int4 ra[2];
    float4 rb[4];

    auto LOADA = [&](int kt) {
#pragma unroll
        for (int i = 0; i < 2; i++) {
            int q = tid + i * 256, r = q >> 2, c8 = q & 3;
            ra[i] = *(const int4*)(Ag + (size_t)r * HID + kt * BK + c8 * 8);
        }
    };
    auto LOADB = [&](int kt) {
#pragma unroll
        for (int i = 0; i < 4; i++) {
            int q = tid + i * 256, r = q >> 3, c4 = q & 7;
            rb[i] = *(const float4*)(Bg + (size_t)r * HID + kt * BK + c4 * 4);
        }
    };
    auto STORE = [&](int buf) {
#pragma unroll
        for (int i = 0; i < 2; i++) {
            int q = tid + i * 256, r = q >> 2, c8 = q & 3;
            *(int4*)&sA[buf][r][c8 * 8] = ra[i];
        }
#pragma unroll
        for (int i = 0; i < 4; i++) {
            int q = tid + i * 256, r = q >> 3, c4 = q & 7;
            *(__half2*)&sB[buf][r][c4 * 4]     = __floats2half2_rn(rb[i].x, rb[i].y);
            *(__half2*)&sB[buf][r][c4 * 4 + 2] = __floats2half2_rn(rb[i].z, rb[i].w);
        }
    };
    auto COMP = [&](int buf) {
#pragma unroll
        for (int ks = 0; ks < 2; ks++) {
            wmma::fragment<wmma::matrix_a, 16, 16, 16, __half, wmma::row_major> a[4];
            wmma::fragment<wmma::matrix_b, 16, 16, 16, __half, wmma::col_major> b[2];
#pragma unroll
            for (int i = 0; i < 4; i++)
                wmma::load_matrix_sync(a[i], &sA[buf][wm * 64 + i * 16][ks * 16], LDSMW);
#pragma unroll
            for (int j = 0; j < 2; j++)
                wmma::load_matrix_sync(b[j], &sB[buf][wn * 32 + j * 16][ks * 16], LDSMW);
#pragma unroll
            for (int i = 0; i < 4; i++)
#pragma unroll
                for (int j = 0; j < 2; j++)
                    wmma::mma_sync(c[i][j], a[i], b[j], c[i][j]);
        }
    };

    LOADA(0); LOADB(0); STORE(0); __syncthreads();
    const int NK = HID / BK;
    for (int kt = 1; kt < NK; kt++) {
        LOADA(kt); LOADB(kt);
        COMP((kt - 1) & 1);
        STORE(kt & 1);
        __syncthreads();
    }
    COMP((NK - 1) & 1);
    __syncthreads();

    float* st = stage_all + warp * 16 * 20;
#pragma unroll
    for (int i = 0; i < 4; i++)
#pragma unroll
        for (int j = 0; j < 2; j++) {
            wmma::store_matrix_sync(st, c[i][j], 20, wmma::mem_row_major);
            __syncwarp();
            int rr = lane >> 1, cbase = (lane & 1) * 8;
            int grow = row0 + wm * 64 + i * 16 + rr;
            if (grow < row_end) {
                int tok = g_perm[grow];
                int gcol = n0 + wn * 32 + j * 16 + cbase;
                float4 o0, o1;
                o0.x = st[rr * 20 + cbase + 0] + bdown[(size_t)e * DIM + gcol + 0];
                o0.y = st[rr * 20 + cbase + 1] + bdown[(size_t)e * DIM + gcol + 1];
                o0.z = st[rr * 20 + cbase + 2] + bdown[(size_t)e * DIM + gcol + 2];
                o0.w = st[rr * 20 + cbase + 3] + bdown[(size_t)e * DIM + gcol + 3];
                o1.x = st[rr * 20 + cbase + 4] + bdown[(size_t)e * DIM + gcol + 4];
                o1.y = st[rr * 20 + cbase + 5] + bdown[(size_t)e * DIM + gcol + 5];
                o1.z = st[rr * 20 + cbase + 6] + bdown[(size_t)e * DIM + gcol + 6];
                o1.w = st[rr * 20 + cbase + 7] + bdown[(size_t)e * DIM + gcol + 7];
                *(float4*)&out[(size_t)tok * DIM + gcol]     = o0;
                *(float4*)&out[(size_t)tok * DIM + gcol + 4] = o1;
            }
            __syncwarp();
        }
#endif
}

// ---------------- host: tensormap encode via dlopen ----------------
typedef CUresult (*encode_fn_t)(CUtensorMap*, CUtensorMapDataType, cuuint32_t, void*,
                                const cuuint64_t*, const cuuint64_t*, const cuuint32_t*,
                                const cuuint32_t*, CUtensorMapInterleave, CUtensorMapSwizzle,
                                CUtensorMapL2promotion, CUtensorMapFloatOOBfill);

static void encode_map(encode_fn_t fn, CUtensorMap* m, void* base,
                       uint64_t d0, uint64_t d1) {
    cuuint64_t dims[2]    = {d0, d1};
    cuuint64_t strides[1] = {d0 * 2};
    cuuint32_t box[2]     = {KC, 256};
    cuuint32_t es[2]      = {1, 1};
    fn(m, CU_TENSOR_MAP_DATA_TYPE_UINT16, 2, base, dims, strides, box, es,
       CU_TENSOR_MAP_INTERLEAVE_NONE, CU_TENSOR_MAP_SWIZZLE_64B,
       CU_TENSOR_MAP_L2_PROMOTION_L2_128B, CU_TENSOR_MAP_FLOAT_OOB_FILL_NONE);
}

// ---------------- launcher ----------------
extern "C" void kernel_launch(void* const* d_in, const int* in_sizes, int n_in,
                              void* d_out, int out_size) {
    const float* x     = (const float*)d_in[0];
    const float* Wr    = (const float*)d_in[1];
    const float* br    = (const float*)d_in[2];
    const float* Wup   = (const float*)d_in[3];
    const float* bup   = (const float*)d_in[4];
    const float* Wdown = (const float*)d_in[5];
    const float* bdown = (const float*)d_in[6];
    float* out = (float*)d_out;

    void* h = dlopen("libcuda.so.1", RTLD_LAZY | RTLD_NOLOAD);
    if (!h) h = dlopen("libcuda.so.1", RTLD_LAZY);
    if (!h) h = dlopen("libcuda.so", RTLD_LAZY);
    encode_fn_t enc = h ? (encode_fn_t)dlsym(h, "cuTensorMapEncodeTiled") : nullptr;

    void *p_xg = nullptr, *p_h = nullptr, *p_wup = nullptr, *p_wdn = nullptr;
    cudaGetSymbolAddress(&p_xg,  g_xg);
    cudaGetSymbolAddress(&p_h,   g_h);
    cudaGetSymbolAddress(&p_wup, g_wup);
    cudaGetSymbolAddress(&p_wdn, g_wdn);

    CUtensorMap tmA_up, tmB_up, tmA_dn, tmB_dn;
    memset(&tmA_up, 0, sizeof(tmA_up));
    memset(&tmB_up, 0, sizeof(tmB_up));
    memset(&tmA_dn, 0, sizeof(tmA_dn));
    memset(&tmB_dn, 0, sizeof(tmB_dn));
    if (enc) {
        encode_map(enc, &tmA_up, p_xg,  DIM, NTOK + PAD);
        encode_map(enc, &tmB_up, p_wup, DIM, (uint64_t)NE * HID);
        encode_map(enc, &tmA_dn, p_h,   HID, NTOK + PAD);
        encode_map(enc, &tmB_dn, p_wdn, HID, (uint64_t)NE * DIM);
    }

    cudaFuncSetAttribute(k_gemm<DIM, true>,  cudaFuncAttributeMaxDynamicSharedMemorySize, SMEM_BYTES);
    cudaFuncSetAttribute(k_gemm<HID, false>, cudaFuncAttributeMaxDynamicSharedMemorySize, SMEM_BYTES);

    k_router<<<NRB, 256>>>(x, Wr, br);                           // + inline last-block scan
    k_gather<<<NRB + NCONV_UP, 256>>>(x, Wup);                   // gather ∥ Wup convert
    k_up<<<dim3(HID / BNW, MAXT), 256>>>(Wup, bup);                                     // empty in 'a'
    k_gemm<DIM, true ><<<dim3(HID / BN, MAXG), 256, SMEM_BYTES>>>(tmA_up, tmB_up, bup, nullptr, Wdown);
    k_gemm<HID, false><<<dim3(DIM / BN, MAXG), 256, SMEM_BYTES>>>(tmA_dn, tmB_dn, bdown, out, nullptr);
    k_down<<<dim3(DIM / BNW, MAXT), 256>>>(Wdown, bdown, out);                          // empty in 'a'
}